// round 8
// baseline (speedup 1.0000x reference)
#include <cuda_runtime.h>
#include <math.h>
#include <stdint.h>

// Problem constants
#define BB 4
#define SS 4096
#define DM 1024
#define HH 16
#define HD 64
#define MTOT (BB*SS)            // 16384
#define NEL (MTOT*DM)           // 16,777,216
#define EPS 1e-6f
#define NBH (BB*HH)             // 64
#define NSPLIT 8

// ---- arch-feature detection: tcgen05 needs the 'a' (or family 'f') target ----
#if defined(__CUDA_ARCH_FEAT_SM103_ALL) || defined(__CUDA_ARCH_FEAT_SM100_ALL) || \
    (defined(__CUDA_ARCH_SPECIFIC__) && (__CUDA_ARCH_SPECIFIC__ == 1030 || __CUDA_ARCH_SPECIFIC__ == 1000)) || \
    (defined(__CUDA_ARCH_FAMILY_SPECIFIC__) && (__CUDA_ARCH_FAMILY_SPECIFIC__ == 1030 || __CUDA_ARCH_FAMILY_SPECIFIC__ == 1000))
#define HAS_TC 1
#else
#define HAS_TC 0
#endif

// tcgen05 GEMM tiling
#define TM 128
#define TN 256
#define BK 32                   // floats per k-chunk = 128 bytes (one SW128 row)
#define NK (DM/BK)              // 32
#define NST 2                   // pipeline stages (2 CTAs/SM)
#define A_STAGE_BYTES (TM*128)  // 16 KB
#define B_STAGE_BYTES (TN*128)  // 32 KB
#define STAGE_BYTES (A_STAGE_BYTES + B_STAGE_BYTES)   // 48 KB
#define SMEM_STAGE0 2048
#define GEMM_SMEM (SMEM_STAGE0 + NST*STAGE_BYTES)     // 100352

// mma.sync fallback tiling
#define MMA_SMEM (4*128*36*4)   // 73728 bytes

// -------- scratch (device globals) --------
__device__ float g_proj[3 * NEL];
__device__ float g_vnew[NEL];
__device__ float g_rw[4 * DM * DM];
__device__ float g_KVpart[NSPLIT * NBH * HD * HD];
__device__ float g_Ksump[NSPLIT * NBH * HD];
__device__ float g_KV[NBH * HD * HD];
__device__ float g_Ksum[NBH * HD];

// ============================================================
// PTX helpers (baseline PTX unless noted)
// ============================================================
__device__ __forceinline__ uint32_t smem_u32(const void* p) {
    uint32_t a;
    asm("{ .reg .u64 t; cvta.to.shared.u64 t, %1; cvt.u32.u64 %0, t; }" : "=r"(a) : "l"(p));
    return a;
}
#define SWZ(o) ((o) ^ (((o) >> 3) & 0x70))

#define CP_ASYNC16(dst, src) \
    asm volatile("cp.async.cg.shared.global [%0], [%1], 16;" :: "r"(dst), "l"(src) : "memory")
#define CP_COMMIT() asm volatile("cp.async.commit_group;" ::: "memory")
#define CP_WAITP()  asm volatile("cp.async.wait_group %0;" :: "n"(NST - 1) : "memory")
#define CP_WAIT1()  asm volatile("cp.async.wait_group 1;" ::: "memory")

#define MBAR_INIT(addr, cnt) \
    asm volatile("mbarrier.init.shared.b64 [%0], %1;" :: "r"(addr), "r"(cnt) : "memory")
__device__ __forceinline__ void mbar_wait(uint32_t addr, uint32_t phase) {
    asm volatile(
        "{\n\t.reg .pred P;\n\t"
        "W_%=:\n\t"
        "mbarrier.try_wait.parity.shared.b64 P, [%0], %1, 0x989680;\n\t"
        "@P bra D_%=;\n\t"
        "bra W_%=;\n\t"
        "D_%=:\n\t}"
        :: "r"(addr), "r"(phase) : "memory");
}

__device__ __forceinline__ float rtf(float x) {
    asm("cvt.rna.tf32.f32 %0, %0;" : "+f"(x));
    return x;
}

#define MMA_TF32(c, a, b) \
    asm volatile("mma.sync.aligned.m16n8k8.row.col.f32.tf32.tf32.f32 " \
        "{%0,%1,%2,%3}, {%4,%5,%6,%7}, {%8,%9}, {%0,%1,%2,%3};" \
        : "+f"((c)[0]), "+f"((c)[1]), "+f"((c)[2]), "+f"((c)[3]) \
        : "r"((a)[0]), "r"((a)[1]), "r"((a)[2]), "r"((a)[3]), \
          "r"((b)[0]), "r"((b)[1]))

#if HAS_TC
#define TC_ALLOC(sm, n)   asm volatile("tcgen05.alloc.cta_group::1.sync.aligned.shared::cta.b32 [%0], %1;" :: "r"(sm), "r"(n) : "memory")
#define TC_DEALLOC(t, n)  asm volatile("tcgen05.dealloc.cta_group::1.sync.aligned.b32 %0, %1;" :: "r"(t), "r"(n))
#define TC_RELINQ()       asm volatile("tcgen05.relinquish_alloc_permit.cta_group::1.sync.aligned;")
#define TC_COMMIT(mb)     asm volatile("tcgen05.commit.cta_group::1.mbarrier::arrive::one.shared::cluster.b64 [%0];" :: "r"(mb) : "memory")
#define TC_FENCE_AFTER()  asm volatile("tcgen05.fence::after_thread_sync;" ::: "memory")
#define TC_WAIT_LD()      asm volatile("tcgen05.wait::ld.sync.aligned;" ::: "memory")
#define FENCE_PROXY()     asm volatile("fence.proxy.async.shared::cta;" ::: "memory")

#define TC_LD_X32(r, ta) \
    asm volatile( \
        "tcgen05.ld.sync.aligned.32x32b.x32.b32 " \
        "{%0, %1, %2, %3, %4, %5, %6, %7, " \
        " %8, %9, %10, %11, %12, %13, %14, %15, " \
        " %16, %17, %18, %19, %20, %21, %22, %23, " \
        " %24, %25, %26, %27, %28, %29, %30, %31}, [%32];" \
        : "=r"((r)[0]),  "=r"((r)[1]),  "=r"((r)[2]),  "=r"((r)[3]), \
          "=r"((r)[4]),  "=r"((r)[5]),  "=r"((r)[6]),  "=r"((r)[7]), \
          "=r"((r)[8]),  "=r"((r)[9]),  "=r"((r)[10]), "=r"((r)[11]), \
          "=r"((r)[12]), "=r"((r)[13]), "=r"((r)[14]), "=r"((r)[15]), \
          "=r"((r)[16]), "=r"((r)[17]), "=r"((r)[18]), "=r"((r)[19]), \
          "=r"((r)[20]), "=r"((r)[21]), "=r"((r)[22]), "=r"((r)[23]), \
          "=r"((r)[24]), "=r"((r)[25]), "=r"((r)[26]), "=r"((r)[27]), \
          "=r"((r)[28]), "=r"((r)[29]), "=r"((r)[30]), "=r"((r)[31]) \
        : "r"(ta))

__device__ __forceinline__ uint64_t make_desc(uint32_t addr) {
    const uint64_t base =
        (uint64_t(2)  << 61) | (uint64_t(1) << 46) | (uint64_t(64) << 32) | (uint64_t(1) << 16);
    return base | ((uint64_t)(addr >> 4) & 0x3FFF);
}

__device__ __forceinline__ void mma_tf32_ss(uint32_t d_tmem, uint64_t a_desc, uint64_t b_desc,
                                            uint32_t idesc, uint32_t enable) {
    asm volatile(
        "{\n\t"
        ".reg .pred p;\n\t"
        "setp.ne.u32 p, %4, 0;\n\t"
        "tcgen05.mma.cta_group::1.kind::tf32 [%0], %1, %2, %3, {%5, %5, %5, %5}, p;\n\t"
        "}"
        :: "r"(d_tmem), "l"(a_desc), "l"(b_desc), "r"(idesc), "r"(enable), "r"(0u)
        : "memory");
}
#endif  // HAS_TC

// ============================================================
// Path A: tcgen05 tf32 GEMM: C[M,N] = A[M,K] @ W[N,K]^T + bias[N]
// Tile 128x256, 128 threads, NST=2 stages, 2 CTAs/SM.
// A is raw fp32 (tf32-truncated by the MMA); W pre-rounded to tf32.
// ============================================================
__global__ __launch_bounds__(128, 2)
void gemm_tf32_kernel(const float* __restrict__ A,
                      const float* __restrict__ W,
                      const float* __restrict__ bias,
                      float* __restrict__ C)
{
#if HAS_TC
    extern __shared__ __align__(1024) char smem[];
    const uint32_t sb = smem_u32(smem);
    const int tid = threadIdx.x;
    const int wid = tid >> 5, lid = tid & 31;
    const int bm0 = blockIdx.y * TM;
    const int bn0 = blockIdx.x * TN;

    float* bsm = (float*)(smem + 128);
    bsm[tid] = bias[bn0 + tid];
    bsm[tid + 128] = bias[bn0 + 128 + tid];

    if (wid == 0) TC_ALLOC(sb + 0, 256);
    if (tid == 0) {
        for (int s = 0; s < NST; s++) MBAR_INIT(sb + 16 + s * 8, 1);
        MBAR_INIT(sb + 16 + NST * 8, 1);
    }
    __syncthreads();
    uint32_t tmem;
    asm volatile("ld.shared.b32 %0, [%1];" : "=r"(tmem) : "r"(sb + 0));

    const float* Abase = A + (size_t)bm0 * DM;
    const float* Wbase = W + (size_t)bn0 * DM;

    const uint32_t idesc = (1u << 4)        // dtype F32
                         | (2u << 7)        // atype TF32
                         | (2u << 10)       // btype TF32
                         | ((TN / 8) << 17)
                         | ((TM / 16) << 24);

    // prologue: stages 0..NST-2
#pragma unroll
    for (int j = 0; j < NST - 1; j++) {
        uint32_t abase = sb + SMEM_STAGE0 + j * STAGE_BYTES;
        uint32_t bbase = abase + A_STAGE_BYTES;
#pragma unroll
        for (int r = 0; r < 8; r++) {
            int i = tid + r * 128; int row = i >> 3, c16 = i & 7;
            CP_ASYNC16(abase + SWZ(row * 128 + c16 * 16),
                       Abase + (size_t)row * DM + j * BK + c16 * 4);
        }
#pragma unroll
        for (int r = 0; r < 16; r++) {
            int i = tid + r * 128; int row = i >> 3, c16 = i & 7;
            CP_ASYNC16(bbase + SWZ(row * 128 + c16 * 16),
                       Wbase + (size_t)row * DM + j * BK + c16 * 4);
        }
        CP_COMMIT();
    }

    for (int kc = 0; kc < NK; kc++) {
        const int j = kc + NST - 1;
        if (j < NK) {
            const int sl = j % NST;
            if (j >= NST) mbar_wait(sb + 16 + sl * 8, ((j / NST) - 1) & 1);
            uint32_t abase = sb + SMEM_STAGE0 + sl * STAGE_BYTES;
            uint32_t bbase = abase + A_STAGE_BYTES;
#pragma unroll
            for (int r = 0; r < 8; r++) {
                int i = tid + r * 128; int row = i >> 3, c16 = i & 7;
                CP_ASYNC16(abase + SWZ(row * 128 + c16 * 16),
                           Abase + (size_t)row * DM + j * BK + c16 * 4);
            }
#pragma unroll
            for (int r = 0; r < 16; r++) {
                int i = tid + r * 128; int row = i >> 3, c16 = i & 7;
                CP_ASYNC16(bbase + SWZ(row * 128 + c16 * 16),
                           Wbase + (size_t)row * DM + j * BK + c16 * 4);
            }
        }
        CP_COMMIT();
        CP_WAITP();
        __syncthreads();
        if (tid == 0) {
            FENCE_PROXY();
            const int sl = kc % NST;
            uint32_t abase = sb + SMEM_STAGE0 + sl * STAGE_BYTES;
            uint64_t ad = make_desc(abase);
            uint64_t bd = make_desc(abase + A_STAGE_BYTES);
#pragma unroll
            for (int t = 0; t < 4; t++)
                mma_tf32_ss(tmem, ad + t * 2, bd + t * 2, idesc, (uint32_t)((kc | t) != 0));
            TC_COMMIT(sb + 16 + sl * 8);
        }
    }
    if (tid == 0) TC_COMMIT(sb + 16 + NST * 8);
    mbar_wait(sb + 16 + NST * 8, 0);
    TC_FENCE_AFTER();

    // epilogue: TMEM -> smem -> gmem, 4 chunks of 64 cols
    float* stg = (float*)(smem + SMEM_STAGE0);
    const int m = wid * 32 + lid;
#pragma unroll 1
    for (int ch = 0; ch < 4; ch++) {
        uint32_t r[64];
        TC_LD_X32(r, tmem + ch * 64);
        TC_LD_X32(r + 32, tmem + ch * 64 + 32);
        TC_WAIT_LD();
        __syncthreads();
#pragma unroll
        for (int c = 0; c < 64; c++)
            stg[m * 65 + c] = __uint_as_float(r[c]) + bsm[ch * 64 + c];
        __syncthreads();
        size_t cb = (size_t)bm0 * DM + bn0 + ch * 64;
#pragma unroll 8
        for (int it = 0; it < 64; it++) {
            int i = tid + it * 128;
            int mm = i >> 6, cc = i & 63;
            C[cb + (size_t)mm * DM + cc] = stg[mm * 65 + cc];
        }
    }
    __syncthreads();
    if (wid == 0) { TC_RELINQ(); TC_DEALLOC(tmem, 256); }
#else
    (void)A; (void)W; (void)bias; (void)C;
#endif
}

// ============================================================
// Path B: mma.sync tf32 fallback GEMM (empty when tcgen05 available)
// ============================================================
__global__ __launch_bounds__(256, 1)
void gemm_mma_kernel(const float* __restrict__ A,
                     const float* __restrict__ W,
                     const float* __restrict__ bias,
                     float* __restrict__ C)
{
#if defined(__CUDA_ARCH__) && !HAS_TC
    extern __shared__ __align__(16) float fsm[];
    float* As = fsm;
    float* Bs = fsm + 2 * 128 * 36;
    const uint32_t as_u = smem_u32(As);
    const uint32_t bs_u = smem_u32(Bs);

    const int tid = threadIdx.x;
    const int lane = tid & 31, warp = tid >> 5;
    const int wm = warp & 3;
    const int wn = warp >> 2;
    const int g = lane >> 2, ti = lane & 3;
    const int bm0 = blockIdx.y * 128;
    const int bn0 = blockIdx.x * 128;

    const float* Ag = A + (size_t)bm0 * DM;
    const float* Wg = W + (size_t)bn0 * DM;

    float c[2][8][4];
#pragma unroll
    for (int mi = 0; mi < 2; mi++)
#pragma unroll
        for (int ni = 0; ni < 8; ni++)
#pragma unroll
            for (int q = 0; q < 4; q++) c[mi][ni][q] = 0.f;

    auto load = [&](int st, int kc) {
        uint32_t ab = as_u + st * (128 * 36 * 4);
        uint32_t bb = bs_u + st * (128 * 36 * 4);
        const float* Ak = Ag + kc * 32;
        const float* Wk = Wg + kc * 32;
#pragma unroll
        for (int r = 0; r < 4; r++) {
            int i = tid + r * 256; int row = i >> 3, cc = i & 7;
            CP_ASYNC16(ab + row * 144 + cc * 16, Ak + (size_t)row * DM + cc * 4);
            CP_ASYNC16(bb + row * 144 + cc * 16, Wk + (size_t)row * DM + cc * 4);
        }
    };

    load(0, 0); CP_COMMIT();
    for (int kc = 0; kc < DM / 32; kc++) {
        if (kc + 1 < DM / 32) load((kc + 1) & 1, kc + 1);
        CP_COMMIT();
        CP_WAIT1();
        __syncthreads();
        const float* as_ = As + (kc & 1) * 128 * 36;
        const float* bs_ = Bs + (kc & 1) * 128 * 36;
#pragma unroll
        for (int ks = 0; ks < 4; ks++) {
            uint32_t a[2][4], b[8][2];
#pragma unroll
            for (int mi = 0; mi < 2; mi++) {
                int r0 = wm * 32 + mi * 16 + g;
                a[mi][0] = __float_as_uint(as_[r0 * 36 + ks * 8 + ti]);
                a[mi][1] = __float_as_uint(as_[(r0 + 8) * 36 + ks * 8 + ti]);
                a[mi][2] = __float_as_uint(as_[r0 * 36 + ks * 8 + ti + 4]);
                a[mi][3] = __float_as_uint(as_[(r0 + 8) * 36 + ks * 8 + ti + 4]);
            }
#pragma unroll
            for (int ni = 0; ni < 8; ni++) {
                int n0 = wn * 64 + ni * 8 + g;
                b[ni][0] = __float_as_uint(bs_[n0 * 36 + ks * 8 + ti]);
                b[ni][1] = __float_as_uint(bs_[n0 * 36 + ks * 8 + ti + 4]);
            }
#pragma unroll
            for (int mi = 0; mi < 2; mi++)
#pragma unroll
                for (int ni = 0; ni < 8; ni++)
                    MMA_TF32(c[mi][ni], a[mi], b[ni]);
        }
        __syncthreads();
    }

#pragma unroll
    for (int mi = 0; mi < 2; mi++) {
        int r0 = bm0 + wm * 32 + mi * 16 + g;
#pragma unroll
        for (int ni = 0; ni < 8; ni++) {
            int c0 = bn0 + wn * 64 + ni * 8 + ti * 2;
            float b0 = bias[c0], b1 = bias[c0 + 1];
            C[(size_t)r0 * DM + c0]           = c[mi][ni][0] + b0;
            C[(size_t)r0 * DM + c0 + 1]       = c[mi][ni][1] + b1;
            C[(size_t)(r0 + 8) * DM + c0]     = c[mi][ni][2] + b0;
            C[(size_t)(r0 + 8) * DM + c0 + 1] = c[mi][ni][3] + b1;
        }
    }
#else
    (void)A; (void)W; (void)bias; (void)C;
#endif
}

// ============================================================
// Round fp32 -> tf32 (RN), vectorized (weights only)
// ============================================================
__global__ void round_tf32_kernel(const float4* __restrict__ x, float4* __restrict__ y)
{
    int i = blockIdx.x * blockDim.x + threadIdx.x;
    float4 v = x[i];
    v.x = rtf(v.x); v.y = rtf(v.y); v.z = rtf(v.z); v.w = rtf(v.w);
    y[i] = v;
}

// ============================================================
// Fused KV accumulation with inline depthwise conv + fmap.
// Reads RAW projections pk, pv; conv applied per 32-row tile in smem.
// KVpart[split][bh][d][e] = sum_s fmap(conv_k(pk))[s,d] * conv_v(pv)[s,e]
// ============================================================
__global__ __launch_bounds__(256)
void kv_accum_kernel(const float* __restrict__ pk, const float* __restrict__ pv,
                     const float* __restrict__ kcw, const float* __restrict__ kcb,
                     const float* __restrict__ vcw, const float* __restrict__ vcb)
{
    const int bh = blockIdx.x;
    const int b = bh / HH, h = bh % HH;
    const int split = blockIdx.y;

    __shared__ float Pk[34 * 64], Pv[34 * 64];
    __shared__ float Ks[32][64], Vs[32][64];
    __shared__ float Wk[192], Bk[64], Wv[192], Bv[64];

    const int t = threadIdx.x;
    if (t < 192) { Wk[t] = kcw[t]; Wv[t] = vcw[t]; }
    if (t < 64)  { Bk[t] = kcb[t]; Bv[t] = vcb[t]; }

    const int d = t >> 2;
    const int e0 = t & 3;

    float acc[16];
#pragma unroll
    for (int j = 0; j < 16; j++) acc[j] = 0.f;
    float ksum = 0.f;

    const size_t base = (size_t)b * SS * DM + h * HD;
    const int sbeg = split * (SS / NSPLIT);

    for (int s0 = sbeg; s0 < sbeg + SS / NSPLIT; s0 += 32) {
        // load raw rows s0-2 .. s0+31 (34 rows x 64 cols)
#pragma unroll
        for (int r = 0; r < 9; r++) {
            int li = r * 256 + t;
            if (li < 34 * 64) {
                int lr = li >> 6, ld = li & 63;
                int s = s0 - 2 + lr;
                float kv_ = 0.f, vv_ = 0.f;
                if (s >= 0) {
                    size_t g = base + (size_t)s * DM + ld;
                    kv_ = pk[g]; vv_ = pv[g];
                }
                Pk[li] = kv_; Pv[li] = vv_;
            }
        }
        __syncthreads();
        // conv + fmap into Ks/Vs
#pragma unroll
        for (int r = 0; r < 8; r++) {
            int li = r * 256 + t;
            int lr = li >> 6, ld = li & 63;
            float kk = Bk[ld] + Wk[ld*3+2]*Pk[(lr+2)*64+ld]
                              + Wk[ld*3+1]*Pk[(lr+1)*64+ld]
                              + Wk[ld*3+0]*Pk[lr*64+ld];
            Ks[lr][ld] = (kk > 0.f) ? (kk + 1.f) : expf(kk);
            float vv = Bv[ld] + Wv[ld*3+2]*Pv[(lr+2)*64+ld]
                              + Wv[ld*3+1]*Pv[(lr+1)*64+ld]
                              + Wv[ld*3+0]*Pv[lr*64+ld];
            Vs[lr][ld] = vv;
        }
        __syncthreads();
#pragma unroll 4
        for (int s = 0; s < 32; s++) {
            float kd = Ks[s][d];
            ksum += kd;
#pragma unroll
            for (int j = 0; j < 16; j++)
                acc[j] += kd * Vs[s][e0 + 4 * j];
        }
        __syncthreads();
    }

    float* kvout = g_KVpart + (((size_t)split * NBH + bh) * HD + d) * HD;
#pragma unroll
    for (int j = 0; j < 16; j++) kvout[e0 + 4 * j] = acc[j];
    if (e0 == 0) g_Ksump[((size_t)split * NBH + bh) * HD + d] = ksum;
}

__global__ void kv_reduce_kernel()
{
    int i = blockIdx.x * blockDim.x + threadIdx.x;
    float s = 0.f;
#pragma unroll
    for (int p = 0; p < NSPLIT; p++) s += g_KVpart[(size_t)p * NBH * HD * HD + i];
    g_KV[i] = s;
    if (i < NBH * HD) {
        float s2 = 0.f;
#pragma unroll
        for (int p = 0; p < NSPLIT; p++) s2 += g_Ksump[p * NBH * HD + i];
        g_Ksum[i] = s2;
    }
}

// ============================================================
// V_new with inline conv+fmap on raw Q projection; tf32-rounded output.
// ============================================================
__global__ __launch_bounds__(256)
void vnew_kernel(const float* __restrict__ pq, float* __restrict__ out,
                 const float* __restrict__ qcw, const float* __restrict__ qcb)
{
    const int bh = blockIdx.x;
    const int b = bh / HH, h = bh % HH;
    const int s0 = blockIdx.y * 32;

    __shared__ float KVs[64 * 64];
    __shared__ float Kss[64];
    __shared__ float Pq[34 * 64];
    __shared__ float Qs[32][64];
    __shared__ float Wq[192], Bq[64];

    const int t = threadIdx.x;
    if (t < 192) Wq[t] = qcw[t];
    if (t < 64)  Bq[t] = qcb[t];

    const float* kvsrc = g_KV + (size_t)bh * HD * HD;
#pragma unroll
    for (int r = 0; r < 16; r++) KVs[r * 256 + t] = kvsrc[r * 256 + t];
    if (t < 64) Kss[t] = g_Ksum[bh * HD + t] + EPS;

    const size_t base = (size_t)b * SS * DM + h * HD;
#pragma unroll
    for (int r = 0; r < 9; r++) {
        int li = r * 256 + t;
        if (li < 34 * 64) {
            int lr = li >> 6, ld = li & 63;
            int s = s0 - 2 + lr;
            Pq[li] = (s >= 0) ? pq[base + (size_t)s * DM + ld] : 0.f;
        }
    }
    __syncthreads();
#pragma unroll
    for (int r = 0; r < 8; r++) {
        int li = r * 256 + t;
        int lr = li >> 6, ld = li & 63;
        float q = Bq[ld] + Wq[ld*3+2]*Pq[(lr+2)*64+ld]
                         + Wq[ld*3+1]*Pq[(lr+1)*64+ld]
                         + Wq[ld*3+0]*Pq[lr*64+ld];
        Qs[lr][ld] = (q > 0.f) ? (q + 1.f) : expf(q);
    }
    __syncthreads();

    const int sl = t >> 3;
    const int e0 = (t & 7) * 8;

    float denom = 0.f;
#pragma unroll
    for (int dd = 0; dd < 64; dd++) denom += Qs[sl][dd] * Kss[dd];
    float zinv = 1.f / denom;

    float acc[8];
#pragma unroll
    for (int j = 0; j < 8; j++) acc[j] = 0.f;
#pragma unroll
    for (int dd = 0; dd < 64; dd++) {
        float qd = Qs[sl][dd];
#pragma unroll
        for (int j = 0; j < 8; j++) acc[j] += KVs[dd * 64 + e0 + j] * qd;
    }

    size_t ob = base + (size_t)(s0 + sl) * DM + e0;
#pragma unroll
    for (int j = 0; j < 8; j++) out[ob + j] = rtf(acc[j] * zinv);
}

// ============================================================
extern "C" void kernel_launch(void* const* d_in, const int* in_sizes, int n_in,
                              void* d_out, int out_size)
{
    const float* query = (const float*)d_in[0];
    const float* key   = (const float*)d_in[1];
    const float* value = (const float*)d_in[2];
    const float* q_w   = (const float*)d_in[3];
    const float* q_b   = (const float*)d_in[4];
    const float* k_w   = (const float*)d_in[5];
    const float* k_b   = (const float*)d_in[6];
    const float* v_w   = (const float*)d_in[7];
    const float* v_b   = (const float*)d_in[8];
    const float* o_w   = (const float*)d_in[9];
    const float* o_b   = (const float*)d_in[10];
    const float* qc_w  = (const float*)d_in[11];
    const float* qc_b  = (const float*)d_in[12];
    const float* kc_w  = (const float*)d_in[13];
    const float* kc_b  = (const float*)d_in[14];
    const float* vc_w  = (const float*)d_in[15];
    const float* vc_b  = (const float*)d_in[16];
    float* out = (float*)d_out;

    float *proj, *vnew, *rw;
    cudaGetSymbolAddress((void**)&proj, g_proj);
    cudaGetSymbolAddress((void**)&vnew, g_vnew);
    cudaGetSymbolAddress((void**)&rw,   g_rw);
    float* pq = proj;  float* pk = proj + (size_t)NEL;  float* pv = proj + 2 * (size_t)NEL;
    float* rqw = rw;                       float* rkw = rw + (size_t)DM * DM;
    float* rvw = rw + 2 * (size_t)DM * DM; float* row_ = rw + 3 * (size_t)DM * DM;

    cudaFuncSetAttribute(gemm_tf32_kernel,
                         cudaFuncAttributeMaxDynamicSharedMemorySize, GEMM_SMEM);
    cudaFuncSetAttribute(gemm_mma_kernel,
                         cudaFuncAttributeMaxDynamicSharedMemorySize, MMA_SMEM);

    const int WN4 = (DM * DM) / 4;

    // 0) round weights to tf32 (RN) — launches 0..3
    round_tf32_kernel<<<WN4 / 256, 256>>>((const float4*)q_w, (float4*)rqw);
    round_tf32_kernel<<<WN4 / 256, 256>>>((const float4*)k_w, (float4*)rkw);
    round_tf32_kernel<<<WN4 / 256, 256>>>((const float4*)v_w, (float4*)rvw);
    round_tf32_kernel<<<WN4 / 256, 256>>>((const float4*)o_w, (float4*)row_);

    dim3 ggrid_tc(DM / TN, MTOT / TM);    // (4, 128)
    dim3 ggrid_mma(DM / 128, MTOT / 128); // (8, 128)

    // mma fallback first so the tcgen05 kernel lands on ncu's profiled
    // launch index (-s 5 => index 5 = first gemm_tf32_kernel).
#define LAUNCH_GEMM(Ain, Win, Bias, Cout) do { \
        gemm_mma_kernel<<<ggrid_mma, 256, MMA_SMEM>>>(Ain, Win, Bias, Cout); \
        gemm_tf32_kernel<<<ggrid_tc, 128, GEMM_SMEM>>>(Ain, Win, Bias, Cout); \
    } while (0)

    // 1) QKV projections on RAW inputs (tf32 truncation inside MMA)
    LAUNCH_GEMM(query, rqw, q_b, pq);     // launches 4,5  (5 = profiled)
    LAUNCH_GEMM(key,   rkw, k_b, pk);
    LAUNCH_GEMM(value, rvw, v_b, pv);

    // 2) KV = conv_k(K)^T conv_v(V) and Ksum (conv fused)
    kv_accum_kernel<<<dim3(NBH, NSPLIT), 256>>>(pk, pv, kc_w, kc_b, vc_w, vc_b);
    kv_reduce_kernel<<<(NBH * HD * HD) / 256, 256>>>();

    // 3) V_new (conv_q fused, tf32-rounded output)
    vnew_kernel<<<dim3(NBH, SS / 32), 256>>>(pq, vnew, qc_w, qc_b);

    // 4) output projection
    LAUNCH_GEMM(vnew, row_, o_b, out);
#undef LAUNCH_GEMM
}

// round 9
// speedup vs baseline: 1.5977x; 1.5977x over previous
#include <cuda_runtime.h>
#include <math.h>
#include <stdint.h>

// Problem constants
#define BB 4
#define SS 4096
#define DM 1024
#define HH 16
#define HD 64
#define MTOT (BB*SS)            // 16384
#define NEL (MTOT*DM)           // 16,777,216
#define EPS 1e-6f
#define NBH (BB*HH)             // 64
#define NSPLIT 8

// ---- arch-feature detection: tcgen05 needs the 'a' (or family 'f') target ----
#if defined(__CUDA_ARCH_FEAT_SM103_ALL) || defined(__CUDA_ARCH_FEAT_SM100_ALL) || \
    (defined(__CUDA_ARCH_SPECIFIC__) && (__CUDA_ARCH_SPECIFIC__ == 1030 || __CUDA_ARCH_SPECIFIC__ == 1000)) || \
    (defined(__CUDA_ARCH_FAMILY_SPECIFIC__) && (__CUDA_ARCH_FAMILY_SPECIFIC__ == 1030 || __CUDA_ARCH_FAMILY_SPECIFIC__ == 1000))
#define HAS_TC 1
#else
#define HAS_TC 0
#endif

// tcgen05 GEMM tiling — PROVEN config from the 1002us run: NST=4, 1 CTA/SM
#define TM 128
#define TN 256
#define BK 32                   // floats per k-chunk = 128 bytes (one SW128 row)
#define NK (DM/BK)              // 32
#define NST 4                   // pipeline stages
#define A_STAGE_BYTES (TM*128)  // 16 KB
#define B_STAGE_BYTES (TN*128)  // 32 KB
#define STAGE_BYTES (A_STAGE_BYTES + B_STAGE_BYTES)   // 48 KB
#define SMEM_STAGE0 2048
#define GEMM_SMEM (SMEM_STAGE0 + NST*STAGE_BYTES)     // 198656

// mma.sync fallback tiling
#define MMA_SMEM (4*128*36*4)   // 73728 bytes

// -------- scratch (device globals) --------
__device__ float g_proj[3 * NEL];
__device__ float g_vnew[NEL];
__device__ float g_rw[4 * DM * DM];
__device__ float g_KVpart[NSPLIT * NBH * HD * HD];
__device__ float g_Ksump[NSPLIT * NBH * HD];
__device__ float g_KV[NBH * HD * HD];
__device__ float g_Ksum[NBH * HD];

// ============================================================
// PTX helpers (baseline PTX unless noted)
// ============================================================
__device__ __forceinline__ uint32_t smem_u32(const void* p) {
    uint32_t a;
    asm("{ .reg .u64 t; cvta.to.shared.u64 t, %1; cvt.u32.u64 %0, t; }" : "=r"(a) : "l"(p));
    return a;
}
#define SWZ(o) ((o) ^ (((o) >> 3) & 0x70))

#define CP_ASYNC16(dst, src) \
    asm volatile("cp.async.cg.shared.global [%0], [%1], 16;" :: "r"(dst), "l"(src) : "memory")
#define CP_COMMIT() asm volatile("cp.async.commit_group;" ::: "memory")
#define CP_WAIT3()  asm volatile("cp.async.wait_group 3;" ::: "memory")
#define CP_WAIT1()  asm volatile("cp.async.wait_group 1;" ::: "memory")

#define MBAR_INIT(addr, cnt) \
    asm volatile("mbarrier.init.shared.b64 [%0], %1;" :: "r"(addr), "r"(cnt) : "memory")
__device__ __forceinline__ void mbar_wait(uint32_t addr, uint32_t phase) {
    asm volatile(
        "{\n\t.reg .pred P;\n\t"
        "W_%=:\n\t"
        "mbarrier.try_wait.parity.shared.b64 P, [%0], %1, 0x989680;\n\t"
        "@P bra D_%=;\n\t"
        "bra W_%=;\n\t"
        "D_%=:\n\t}"
        :: "r"(addr), "r"(phase) : "memory");
}

__device__ __forceinline__ float rtf(float x) {
    asm("cvt.rna.tf32.f32 %0, %0;" : "+f"(x));
    return x;
}

#define MMA_TF32(c, a, b) \
    asm volatile("mma.sync.aligned.m16n8k8.row.col.f32.tf32.tf32.f32 " \
        "{%0,%1,%2,%3}, {%4,%5,%6,%7}, {%8,%9}, {%0,%1,%2,%3};" \
        : "+f"((c)[0]), "+f"((c)[1]), "+f"((c)[2]), "+f"((c)[3]) \
        : "r"((a)[0]), "r"((a)[1]), "r"((a)[2]), "r"((a)[3]), \
          "r"((b)[0]), "r"((b)[1]))

#if HAS_TC
#define TC_ALLOC(sm, n)   asm volatile("tcgen05.alloc.cta_group::1.sync.aligned.shared::cta.b32 [%0], %1;" :: "r"(sm), "r"(n) : "memory")
#define TC_DEALLOC(t, n)  asm volatile("tcgen05.dealloc.cta_group::1.sync.aligned.b32 %0, %1;" :: "r"(t), "r"(n))
#define TC_RELINQ()       asm volatile("tcgen05.relinquish_alloc_permit.cta_group::1.sync.aligned;")
#define TC_COMMIT(mb)     asm volatile("tcgen05.commit.cta_group::1.mbarrier::arrive::one.shared::cluster.b64 [%0];" :: "r"(mb) : "memory")
#define TC_FENCE_AFTER()  asm volatile("tcgen05.fence::after_thread_sync;" ::: "memory")
#define TC_WAIT_LD()      asm volatile("tcgen05.wait::ld.sync.aligned;" ::: "memory")
#define FENCE_PROXY()     asm volatile("fence.proxy.async.shared::cta;" ::: "memory")

#define TC_LD_X32(r, ta) \
    asm volatile( \
        "tcgen05.ld.sync.aligned.32x32b.x32.b32 " \
        "{%0, %1, %2, %3, %4, %5, %6, %7, " \
        " %8, %9, %10, %11, %12, %13, %14, %15, " \
        " %16, %17, %18, %19, %20, %21, %22, %23, " \
        " %24, %25, %26, %27, %28, %29, %30, %31}, [%32];" \
        : "=r"((r)[0]),  "=r"((r)[1]),  "=r"((r)[2]),  "=r"((r)[3]), \
          "=r"((r)[4]),  "=r"((r)[5]),  "=r"((r)[6]),  "=r"((r)[7]), \
          "=r"((r)[8]),  "=r"((r)[9]),  "=r"((r)[10]), "=r"((r)[11]), \
          "=r"((r)[12]), "=r"((r)[13]), "=r"((r)[14]), "=r"((r)[15]), \
          "=r"((r)[16]), "=r"((r)[17]), "=r"((r)[18]), "=r"((r)[19]), \
          "=r"((r)[20]), "=r"((r)[21]), "=r"((r)[22]), "=r"((r)[23]), \
          "=r"((r)[24]), "=r"((r)[25]), "=r"((r)[26]), "=r"((r)[27]), \
          "=r"((r)[28]), "=r"((r)[29]), "=r"((r)[30]), "=r"((r)[31]) \
        : "r"(ta))

__device__ __forceinline__ uint64_t make_desc(uint32_t addr) {
    const uint64_t base =
        (uint64_t(2)  << 61) | (uint64_t(1) << 46) | (uint64_t(64) << 32) | (uint64_t(1) << 16);
    return base | ((uint64_t)(addr >> 4) & 0x3FFF);
}

__device__ __forceinline__ void mma_tf32_ss(uint32_t d_tmem, uint64_t a_desc, uint64_t b_desc,
                                            uint32_t idesc, uint32_t enable) {
    asm volatile(
        "{\n\t"
        ".reg .pred p;\n\t"
        "setp.ne.u32 p, %4, 0;\n\t"
        "tcgen05.mma.cta_group::1.kind::tf32 [%0], %1, %2, %3, {%5, %5, %5, %5}, p;\n\t"
        "}"
        :: "r"(d_tmem), "l"(a_desc), "l"(b_desc), "r"(idesc), "r"(enable), "r"(0u)
        : "memory");
}
#endif  // HAS_TC

// ============================================================
// Path A: tcgen05 tf32 GEMM: C[M,N] = A[M,K] @ W[N,K]^T + bias[N]
// Tile 128x256, 128 threads, NST=4 stages (proven 1002us config).
// A raw fp32 (tf32-truncated in MMA); W pre-rounded to tf32.
// ============================================================
__global__ __launch_bounds__(128, 1)
void gemm_tf32_kernel(const float* __restrict__ A,
                      const float* __restrict__ W,
                      const float* __restrict__ bias,
                      float* __restrict__ C)
{
#if HAS_TC
    extern __shared__ __align__(1024) char smem[];
    const uint32_t sb = smem_u32(smem);
    const int tid = threadIdx.x;
    const int wid = tid >> 5, lid = tid & 31;
    const int bm0 = blockIdx.y * TM;
    const int bn0 = blockIdx.x * TN;

    float* bsm = (float*)(smem + 128);
    bsm[tid] = bias[bn0 + tid];
    bsm[tid + 128] = bias[bn0 + 128 + tid];

    if (wid == 0) TC_ALLOC(sb + 0, 256);
    if (tid == 0) {
        for (int s = 0; s < NST; s++) MBAR_INIT(sb + 16 + s * 8, 1);
        MBAR_INIT(sb + 16 + NST * 8, 1);
    }
    __syncthreads();
    uint32_t tmem;
    asm volatile("ld.shared.b32 %0, [%1];" : "=r"(tmem) : "r"(sb + 0));

    const float* Abase = A + (size_t)bm0 * DM;
    const float* Wbase = W + (size_t)bn0 * DM;

    const uint32_t idesc = (1u << 4)        // dtype F32
                         | (2u << 7)        // atype TF32
                         | (2u << 10)       // btype TF32
                         | ((TN / 8) << 17)
                         | ((TM / 16) << 24);

    // prologue: stages 0..NST-2
#pragma unroll
    for (int j = 0; j < NST - 1; j++) {
        uint32_t abase = sb + SMEM_STAGE0 + j * STAGE_BYTES;
        uint32_t bbase = abase + A_STAGE_BYTES;
#pragma unroll
        for (int r = 0; r < 8; r++) {
            int i = tid + r * 128; int row = i >> 3, c16 = i & 7;
            CP_ASYNC16(abase + SWZ(row * 128 + c16 * 16),
                       Abase + (size_t)row * DM + j * BK + c16 * 4);
        }
#pragma unroll
        for (int r = 0; r < 16; r++) {
            int i = tid + r * 128; int row = i >> 3, c16 = i & 7;
            CP_ASYNC16(bbase + SWZ(row * 128 + c16 * 16),
                       Wbase + (size_t)row * DM + j * BK + c16 * 4);
        }
        CP_COMMIT();
    }

    for (int kc = 0; kc < NK; kc++) {
        const int j = kc + NST - 1;
        if (j < NK) {
            const int sl = j & (NST - 1);
            if (j >= NST) mbar_wait(sb + 16 + sl * 8, ((j >> 2) - 1) & 1);
            uint32_t abase = sb + SMEM_STAGE0 + sl * STAGE_BYTES;
            uint32_t bbase = abase + A_STAGE_BYTES;
#pragma unroll
            for (int r = 0; r < 8; r++) {
                int i = tid + r * 128; int row = i >> 3, c16 = i & 7;
                CP_ASYNC16(abase + SWZ(row * 128 + c16 * 16),
                           Abase + (size_t)row * DM + j * BK + c16 * 4);
            }
#pragma unroll
            for (int r = 0; r < 16; r++) {
                int i = tid + r * 128; int row = i >> 3, c16 = i & 7;
                CP_ASYNC16(bbase + SWZ(row * 128 + c16 * 16),
                           Wbase + (size_t)row * DM + j * BK + c16 * 4);
            }
        }
        CP_COMMIT();
        CP_WAIT3();
        __syncthreads();
        if (tid == 0) {
            FENCE_PROXY();
            const int sl = kc & (NST - 1);
            uint32_t abase = sb + SMEM_STAGE0 + sl * STAGE_BYTES;
            uint64_t ad = make_desc(abase);
            uint64_t bd = make_desc(abase + A_STAGE_BYTES);
#pragma unroll
            for (int t = 0; t < 4; t++)
                mma_tf32_ss(tmem, ad + t * 2, bd + t * 2, idesc, (uint32_t)((kc | t) != 0));
            TC_COMMIT(sb + 16 + sl * 8);
        }
    }
    if (tid == 0) TC_COMMIT(sb + 16 + NST * 8);
    mbar_wait(sb + 16 + NST * 8, 0);
    TC_FENCE_AFTER();

    // epilogue: TMEM -> smem -> gmem, 4 chunks of 64 cols
    float* stg = (float*)(smem + SMEM_STAGE0);
    const int m = wid * 32 + lid;
#pragma unroll 1
    for (int ch = 0; ch < 4; ch++) {
        uint32_t r[64];
        TC_LD_X32(r, tmem + ch * 64);
        TC_LD_X32(r + 32, tmem + ch * 64 + 32);
        TC_WAIT_LD();
        __syncthreads();
#pragma unroll
        for (int c = 0; c < 64; c++)
            stg[m * 65 + c] = __uint_as_float(r[c]) + bsm[ch * 64 + c];
        __syncthreads();
        size_t cb = (size_t)bm0 * DM + bn0 + ch * 64;
#pragma unroll 8
        for (int it = 0; it < 64; it++) {
            int i = tid + it * 128;
            int mm = i >> 6, cc = i & 63;
            C[cb + (size_t)mm * DM + cc] = stg[mm * 65 + cc];
        }
    }
    __syncthreads();
    if (wid == 0) { TC_RELINQ(); TC_DEALLOC(tmem, 256); }
#else
    (void)A; (void)W; (void)bias; (void)C;
#endif
}

// ============================================================
// Path B: mma.sync tf32 fallback GEMM (empty when tcgen05 available)
// ============================================================
__global__ __launch_bounds__(256, 1)
void gemm_mma_kernel(const float* __restrict__ A,
                     const float* __restrict__ W,
                     const float* __restrict__ bias,
                     float* __restrict__ C)
{
#if defined(__CUDA_ARCH__) && !HAS_TC
    extern __shared__ __align__(16) float fsm[];
    float* As = fsm;
    float* Bs = fsm + 2 * 128 * 36;
    const uint32_t as_u = smem_u32(As);
    const uint32_t bs_u = smem_u32(Bs);

    const int tid = threadIdx.x;
    const int lane = tid & 31, warp = tid >> 5;
    const int wm = warp & 3;
    const int wn = warp >> 2;
    const int g = lane >> 2, ti = lane & 3;
    const int bm0 = blockIdx.y * 128;
    const int bn0 = blockIdx.x * 128;

    const float* Ag = A + (size_t)bm0 * DM;
    const float* Wg = W + (size_t)bn0 * DM;

    float c[2][8][4];
#pragma unroll
    for (int mi = 0; mi < 2; mi++)
#pragma unroll
        for (int ni = 0; ni < 8; ni++)
#pragma unroll
            for (int q = 0; q < 4; q++) c[mi][ni][q] = 0.f;

    auto load = [&](int st, int kc) {
        uint32_t ab = as_u + st * (128 * 36 * 4);
        uint32_t bb = bs_u + st * (128 * 36 * 4);
        const float* Ak = Ag + kc * 32;
        const float* Wk = Wg + kc * 32;
#pragma unroll
        for (int r = 0; r < 4; r++) {
            int i = tid + r * 256; int row = i >> 3, cc = i & 7;
            CP_ASYNC16(ab + row * 144 + cc * 16, Ak + (size_t)row * DM + cc * 4);
            CP_ASYNC16(bb + row * 144 + cc * 16, Wk + (size_t)row * DM + cc * 4);
        }
    };

    load(0, 0); CP_COMMIT();
    for (int kc = 0; kc < DM / 32; kc++) {
        if (kc + 1 < DM / 32) load((kc + 1) & 1, kc + 1);
        CP_COMMIT();
        CP_WAIT1();
        __syncthreads();
        const float* as_ = As + (kc & 1) * 128 * 36;
        const float* bs_ = Bs + (kc & 1) * 128 * 36;
#pragma unroll
        for (int ks = 0; ks < 4; ks++) {
            uint32_t a[2][4], b[8][2];
#pragma unroll
            for (int mi = 0; mi < 2; mi++) {
                int r0 = wm * 32 + mi * 16 + g;
                a[mi][0] = __float_as_uint(as_[r0 * 36 + ks * 8 + ti]);
                a[mi][1] = __float_as_uint(as_[(r0 + 8) * 36 + ks * 8 + ti]);
                a[mi][2] = __float_as_uint(as_[r0 * 36 + ks * 8 + ti + 4]);
                a[mi][3] = __float_as_uint(as_[(r0 + 8) * 36 + ks * 8 + ti + 4]);
            }
#pragma unroll
            for (int ni = 0; ni < 8; ni++) {
                int n0 = wn * 64 + ni * 8 + g;
                b[ni][0] = __float_as_uint(bs_[n0 * 36 + ks * 8 + ti]);
                b[ni][1] = __float_as_uint(bs_[n0 * 36 + ks * 8 + ti + 4]);
            }
#pragma unroll
            for (int mi = 0; mi < 2; mi++)
#pragma unroll
                for (int ni = 0; ni < 8; ni++)
                    MMA_TF32(c[mi][ni], a[mi], b[ni]);
        }
        __syncthreads();
    }

#pragma unroll
    for (int mi = 0; mi < 2; mi++) {
        int r0 = bm0 + wm * 32 + mi * 16 + g;
#pragma unroll
        for (int ni = 0; ni < 8; ni++) {
            int c0 = bn0 + wn * 64 + ni * 8 + ti * 2;
            float b0 = bias[c0], b1 = bias[c0 + 1];
            C[(size_t)r0 * DM + c0]           = c[mi][ni][0] + b0;
            C[(size_t)r0 * DM + c0 + 1]       = c[mi][ni][1] + b1;
            C[(size_t)(r0 + 8) * DM + c0]     = c[mi][ni][2] + b0;
            C[(size_t)(r0 + 8) * DM + c0 + 1] = c[mi][ni][3] + b1;
        }
    }
#else
    (void)A; (void)W; (void)bias; (void)C;
#endif
}

// ============================================================
// Round fp32 -> tf32 (RN), vectorized (weights only)
// ============================================================
__global__ void round_tf32_kernel(const float4* __restrict__ x, float4* __restrict__ y)
{
    int i = blockIdx.x * blockDim.x + threadIdx.x;
    float4 v = x[i];
    v.x = rtf(v.x); v.y = rtf(v.y); v.z = rtf(v.z); v.w = rtf(v.w);
    y[i] = v;
}

// ============================================================
// Fused KV accumulation with inline depthwise conv + fmap.
// ============================================================
__global__ __launch_bounds__(256)
void kv_accum_kernel(const float* __restrict__ pk, const float* __restrict__ pv,
                     const float* __restrict__ kcw, const float* __restrict__ kcb,
                     const float* __restrict__ vcw, const float* __restrict__ vcb)
{
    const int bh = blockIdx.x;
    const int b = bh / HH, h = bh % HH;
    const int split = blockIdx.y;

    __shared__ float Pk[34 * 64], Pv[34 * 64];
    __shared__ float Ks[32][64], Vs[32][64];
    __shared__ float Wk[192], Bk[64], Wv[192], Bv[64];

    const int t = threadIdx.x;
    if (t < 192) { Wk[t] = kcw[t]; Wv[t] = vcw[t]; }
    if (t < 64)  { Bk[t] = kcb[t]; Bv[t] = vcb[t]; }

    const int d = t >> 2;
    const int e0 = t & 3;

    float acc[16];
#pragma unroll
    for (int j = 0; j < 16; j++) acc[j] = 0.f;
    float ksum = 0.f;

    const size_t base = (size_t)b * SS * DM + h * HD;
    const int sbeg = split * (SS / NSPLIT);

    for (int s0 = sbeg; s0 < sbeg + SS / NSPLIT; s0 += 32) {
#pragma unroll
        for (int r = 0; r < 9; r++) {
            int li = r * 256 + t;
            if (li < 34 * 64) {
                int lr = li >> 6, ld = li & 63;
                int s = s0 - 2 + lr;
                float kv_ = 0.f, vv_ = 0.f;
                if (s >= 0) {
                    size_t g = base + (size_t)s * DM + ld;
                    kv_ = pk[g]; vv_ = pv[g];
                }
                Pk[li] = kv_; Pv[li] = vv_;
            }
        }
        __syncthreads();
#pragma unroll
        for (int r = 0; r < 8; r++) {
            int li = r * 256 + t;
            int lr = li >> 6, ld = li & 63;
            float kk = Bk[ld] + Wk[ld*3+2]*Pk[(lr+2)*64+ld]
                              + Wk[ld*3+1]*Pk[(lr+1)*64+ld]
                              + Wk[ld*3+0]*Pk[lr*64+ld];
            Ks[lr][ld] = (kk > 0.f) ? (kk + 1.f) : expf(kk);
            float vv = Bv[ld] + Wv[ld*3+2]*Pv[(lr+2)*64+ld]
                              + Wv[ld*3+1]*Pv[(lr+1)*64+ld]
                              + Wv[ld*3+0]*Pv[lr*64+ld];
            Vs[lr][ld] = vv;
        }
        __syncthreads();
#pragma unroll 4
        for (int s = 0; s < 32; s++) {
            float kd = Ks[s][d];
            ksum += kd;
#pragma unroll
            for (int j = 0; j < 16; j++)
                acc[j] += kd * Vs[s][e0 + 4 * j];
        }
        __syncthreads();
    }

    float* kvout = g_KVpart + (((size_t)split * NBH + bh) * HD + d) * HD;
#pragma unroll
    for (int j = 0; j < 16; j++) kvout[e0 + 4 * j] = acc[j];
    if (e0 == 0) g_Ksump[((size_t)split * NBH + bh) * HD + d] = ksum;
}

__global__ void kv_reduce_kernel()
{
    int i = blockIdx.x * blockDim.x + threadIdx.x;
    float s = 0.f;
#pragma unroll
    for (int p = 0; p < NSPLIT; p++) s += g_KVpart[(size_t)p * NBH * HD * HD + i];
    g_KV[i] = s;
    if (i < NBH * HD) {
        float s2 = 0.f;
#pragma unroll
        for (int p = 0; p < NSPLIT; p++) s2 += g_Ksump[p * NBH * HD + i];
        g_Ksum[i] = s2;
    }
}

// ============================================================
// V_new with inline conv+fmap on raw Q projection; tf32-rounded output.
// ============================================================
__global__ __launch_bounds__(256)
void vnew_kernel(const float* __restrict__ pq, float* __restrict__ out,
                 const float* __restrict__ qcw, const float* __restrict__ qcb)
{
    const int bh = blockIdx.x;
    const int b = bh / HH, h = bh % HH;
    const int s0 = blockIdx.y * 32;

    __shared__ float KVs[64 * 64];
    __shared__ float Kss[64];
    __shared__ float Pq[34 * 64];
    __shared__ float Qs[32][64];
    __shared__ float Wq[192], Bq[64];

    const int t = threadIdx.x;
    if (t < 192) Wq[t] = qcw[t];
    if (t < 64)  Bq[t] = qcb[t];

    const float* kvsrc = g_KV + (size_t)bh * HD * HD;
#pragma unroll
    for (int r = 0; r < 16; r++) KVs[r * 256 + t] = kvsrc[r * 256 + t];
    if (t < 64) Kss[t] = g_Ksum[bh * HD + t] + EPS;

    const size_t base = (size_t)b * SS * DM + h * HD;
#pragma unroll
    for (int r = 0; r < 9; r++) {
        int li = r * 256 + t;
        if (li < 34 * 64) {
            int lr = li >> 6, ld = li & 63;
            int s = s0 - 2 + lr;
            Pq[li] = (s >= 0) ? pq[base + (size_t)s * DM + ld] : 0.f;
        }
    }
    __syncthreads();
#pragma unroll
    for (int r = 0; r < 8; r++) {
        int li = r * 256 + t;
        int lr = li >> 6, ld = li & 63;
        float q = Bq[ld] + Wq[ld*3+2]*Pq[(lr+2)*64+ld]
                         + Wq[ld*3+1]*Pq[(lr+1)*64+ld]
                         + Wq[ld*3+0]*Pq[lr*64+ld];
        Qs[lr][ld] = (q > 0.f) ? (q + 1.f) : expf(q);
    }
    __syncthreads();

    const int sl = t >> 3;
    const int e0 = (t & 7) * 8;

    float denom = 0.f;
#pragma unroll
    for (int dd = 0; dd < 64; dd++) denom += Qs[sl][dd] * Kss[dd];
    float zinv = 1.f / denom;

    float acc[8];
#pragma unroll
    for (int j = 0; j < 8; j++) acc[j] = 0.f;
#pragma unroll
    for (int dd = 0; dd < 64; dd++) {
        float qd = Qs[sl][dd];
#pragma unroll
        for (int j = 0; j < 8; j++) acc[j] += KVs[dd * 64 + e0 + j] * qd;
    }

    size_t ob = base + (size_t)(s0 + sl) * DM + e0;
#pragma unroll
    for (int j = 0; j < 8; j++) out[ob + j] = rtf(acc[j] * zinv);
}

// ============================================================
extern "C" void kernel_launch(void* const* d_in, const int* in_sizes, int n_in,
                              void* d_out, int out_size)
{
    const float* query = (const float*)d_in[0];
    const float* key   = (const float*)d_in[1];
    const float* value = (const float*)d_in[2];
    const float* q_w   = (const float*)d_in[3];
    const float* q_b   = (const float*)d_in[4];
    const float* k_w   = (const float*)d_in[5];
    const float* k_b   = (const float*)d_in[6];
    const float* v_w   = (const float*)d_in[7];
    const float* v_b   = (const float*)d_in[8];
    const float* o_w   = (const float*)d_in[9];
    const float* o_b   = (const float*)d_in[10];
    const float* qc_w  = (const float*)d_in[11];
    const float* qc_b  = (const float*)d_in[12];
    const float* kc_w  = (const float*)d_in[13];
    const float* kc_b  = (const float*)d_in[14];
    const float* vc_w  = (const float*)d_in[15];
    const float* vc_b  = (const float*)d_in[16];
    float* out = (float*)d_out;

    float *proj, *vnew, *rw;
    cudaGetSymbolAddress((void**)&proj, g_proj);
    cudaGetSymbolAddress((void**)&vnew, g_vnew);
    cudaGetSymbolAddress((void**)&rw,   g_rw);
    float* pq = proj;  float* pk = proj + (size_t)NEL;  float* pv = proj + 2 * (size_t)NEL;
    float* rqw = rw;                       float* rkw = rw + (size_t)DM * DM;
    float* rvw = rw + 2 * (size_t)DM * DM; float* row_ = rw + 3 * (size_t)DM * DM;

    cudaFuncSetAttribute(gemm_tf32_kernel,
                         cudaFuncAttributeMaxDynamicSharedMemorySize, GEMM_SMEM);
    cudaFuncSetAttribute(gemm_mma_kernel,
                         cudaFuncAttributeMaxDynamicSharedMemorySize, MMA_SMEM);

    const int WN4 = (DM * DM) / 4;

    // 0) round weights to tf32 (RN)
    round_tf32_kernel<<<WN4 / 256, 256>>>((const float4*)q_w, (float4*)rqw);
    round_tf32_kernel<<<WN4 / 256, 256>>>((const float4*)k_w, (float4*)rkw);
    round_tf32_kernel<<<WN4 / 256, 256>>>((const float4*)v_w, (float4*)rvw);
    round_tf32_kernel<<<WN4 / 256, 256>>>((const float4*)o_w, (float4*)row_);

    dim3 ggrid_tc(DM / TN, MTOT / TM);    // (4, 128)
    dim3 ggrid_mma(DM / 128, MTOT / 128); // (8, 128)

#define LAUNCH_GEMM(Ain, Win, Bias, Cout) do { \
        gemm_mma_kernel<<<ggrid_mma, 256, MMA_SMEM>>>(Ain, Win, Bias, Cout); \
        gemm_tf32_kernel<<<ggrid_tc, 128, GEMM_SMEM>>>(Ain, Win, Bias, Cout); \
    } while (0)

    // 1) QKV projections on RAW inputs (tf32 truncation inside MMA)
    LAUNCH_GEMM(query, rqw, q_b, pq);
    LAUNCH_GEMM(key,   rkw, k_b, pk);
    LAUNCH_GEMM(value, rvw, v_b, pv);

    // 2) KV = conv_k(K)^T conv_v(V) and Ksum (conv fused)
    kv_accum_kernel<<<dim3(NBH, NSPLIT), 256>>>(pk, pv, kc_w, kc_b, vc_w, vc_b);
    kv_reduce_kernel<<<(NBH * HD * HD) / 256, 256>>>();

    // 3) V_new (conv_q fused, tf32-rounded output)
    vnew_kernel<<<dim3(NBH, SS / 32), 256>>>(pq, vnew, qc_w, qc_b);

    // 4) output projection
    LAUNCH_GEMM(vnew, row_, o_b, out);
#undef LAUNCH_GEMM
}

// round 10
// speedup vs baseline: 1.6172x; 1.0122x over previous
#include <cuda_runtime.h>
#include <cuda.h>
#include <math.h>
#include <stdint.h>

// Problem constants
#define BB 4
#define SS 4096
#define DM 1024
#define HH 16
#define HD 64
#define MTOT (BB*SS)            // 16384
#define NEL (MTOT*DM)           // 16,777,216
#define EPS 1e-6f
#define NBH (BB*HH)             // 64
#define NSPLIT 8

// ---- arch-feature detection: tcgen05 needs the 'a' (or family 'f') target ----
#if defined(__CUDA_ARCH_FEAT_SM103_ALL) || defined(__CUDA_ARCH_FEAT_SM100_ALL) || \
    (defined(__CUDA_ARCH_SPECIFIC__) && (__CUDA_ARCH_SPECIFIC__ == 1030 || __CUDA_ARCH_SPECIFIC__ == 1000)) || \
    (defined(__CUDA_ARCH_FAMILY_SPECIFIC__) && (__CUDA_ARCH_FAMILY_SPECIFIC__ == 1030 || __CUDA_ARCH_FAMILY_SPECIFIC__ == 1000))
#define HAS_TC 1
#else
#define HAS_TC 0
#endif

// tcgen05 GEMM tiling
#define TM 128
#define TN 256
#define BK 32                   // floats per k-chunk = 128 bytes (one SW128 row)
#define NK (DM/BK)              // 32
#define NST 4                   // pipeline stages
#define A_STAGE_BYTES (TM*128)  // 16 KB
#define B_STAGE_BYTES (TN*128)  // 32 KB
#define STAGE_BYTES (A_STAGE_BYTES + B_STAGE_BYTES)   // 48 KB
#define SMEM_STAGE0 2048
#define GEMM_SMEM (SMEM_STAGE0 + NST*STAGE_BYTES)     // 198656

// mma.sync fallback tiling
#define MMA_SMEM (4*128*36*4)   // 73728 bytes

// -------- scratch (device globals) --------
__device__ float g_proj[3 * NEL];
__device__ float g_vnew[NEL];
__device__ float g_rw[4 * DM * DM];
__device__ float g_KVpart[NSPLIT * NBH * HD * HD];
__device__ float g_Ksump[NSPLIT * NBH * HD];
__device__ float g_KV[NBH * HD * HD];
__device__ float g_Ksum[NBH * HD];

// ============================================================
// PTX helpers (baseline PTX unless noted)
// ============================================================
__device__ __forceinline__ uint32_t smem_u32(const void* p) {
    uint32_t a;
    asm("{ .reg .u64 t; cvta.to.shared.u64 t, %1; cvt.u32.u64 %0, t; }" : "=r"(a) : "l"(p));
    return a;
}
#define SWZ(o) ((o) ^ (((o) >> 3) & 0x70))

#define CP_ASYNC16(dst, src) \
    asm volatile("cp.async.cg.shared.global [%0], [%1], 16;" :: "r"(dst), "l"(src) : "memory")
#define CP_COMMIT() asm volatile("cp.async.commit_group;" ::: "memory")
#define CP_WAIT3()  asm volatile("cp.async.wait_group 3;" ::: "memory")
#define CP_WAIT1()  asm volatile("cp.async.wait_group 1;" ::: "memory")

#define MBAR_INIT(addr, cnt) \
    asm volatile("mbarrier.init.shared.b64 [%0], %1;" :: "r"(addr), "r"(cnt) : "memory")
#define MBAR_EXPECT_TX(addr, bytes) \
    asm volatile("mbarrier.arrive.expect_tx.shared.b64 _, [%0], %1;" :: "r"(addr), "r"(bytes) : "memory")
#define MBAR_ARRIVE(addr) \
    asm volatile("mbarrier.arrive.shared.b64 _, [%0];" :: "r"(addr) : "memory")
__device__ __forceinline__ void mbar_wait(uint32_t addr, uint32_t phase) {
    asm volatile(
        "{\n\t.reg .pred P;\n\t"
        "W_%=:\n\t"
        "mbarrier.try_wait.parity.shared.b64 P, [%0], %1, 0x989680;\n\t"
        "@P bra D_%=;\n\t"
        "bra W_%=;\n\t"
        "D_%=:\n\t}"
        :: "r"(addr), "r"(phase) : "memory");
}

__device__ __forceinline__ float rtf(float x) {
    asm("cvt.rna.tf32.f32 %0, %0;" : "+f"(x));
    return x;
}

#define MMA_TF32(c, a, b) \
    asm volatile("mma.sync.aligned.m16n8k8.row.col.f32.tf32.tf32.f32 " \
        "{%0,%1,%2,%3}, {%4,%5,%6,%7}, {%8,%9}, {%0,%1,%2,%3};" \
        : "+f"((c)[0]), "+f"((c)[1]), "+f"((c)[2]), "+f"((c)[3]) \
        : "r"((a)[0]), "r"((a)[1]), "r"((a)[2]), "r"((a)[3]), \
          "r"((b)[0]), "r"((b)[1]))

#if HAS_TC
#define TC_ALLOC(sm, n)   asm volatile("tcgen05.alloc.cta_group::1.sync.aligned.shared::cta.b32 [%0], %1;" :: "r"(sm), "r"(n) : "memory")
#define TC_DEALLOC(t, n)  asm volatile("tcgen05.dealloc.cta_group::1.sync.aligned.b32 %0, %1;" :: "r"(t), "r"(n))
#define TC_RELINQ()       asm volatile("tcgen05.relinquish_alloc_permit.cta_group::1.sync.aligned;")
#define TC_COMMIT(mb)     asm volatile("tcgen05.commit.cta_group::1.mbarrier::arrive::one.shared::cluster.b64 [%0];" :: "r"(mb) : "memory")
#define TC_FENCE_AFTER()  asm volatile("tcgen05.fence::after_thread_sync;" ::: "memory")
#define TC_WAIT_LD()      asm volatile("tcgen05.wait::ld.sync.aligned;" ::: "memory")
#define FENCE_PROXY()     asm volatile("fence.proxy.async.shared::cta;" ::: "memory")

#define TMA_LD_2D(smem, map, x, y, mb) \
    asm volatile("cp.async.bulk.tensor.2d.shared::cta.global.tile.mbarrier::complete_tx::bytes " \
        "[%0], [%1, {%2, %3}], [%4];" \
        :: "r"(smem), "l"(map), "r"(x), "r"(y), "r"(mb) : "memory")

#define TC_LD_X32(r, ta) \
    asm volatile( \
        "tcgen05.ld.sync.aligned.32x32b.x32.b32 " \
        "{%0, %1, %2, %3, %4, %5, %6, %7, " \
        " %8, %9, %10, %11, %12, %13, %14, %15, " \
        " %16, %17, %18, %19, %20, %21, %22, %23, " \
        " %24, %25, %26, %27, %28, %29, %30, %31}, [%32];" \
        : "=r"((r)[0]),  "=r"((r)[1]),  "=r"((r)[2]),  "=r"((r)[3]), \
          "=r"((r)[4]),  "=r"((r)[5]),  "=r"((r)[6]),  "=r"((r)[7]), \
          "=r"((r)[8]),  "=r"((r)[9]),  "=r"((r)[10]), "=r"((r)[11]), \
          "=r"((r)[12]), "=r"((r)[13]), "=r"((r)[14]), "=r"((r)[15]), \
          "=r"((r)[16]), "=r"((r)[17]), "=r"((r)[18]), "=r"((r)[19]), \
          "=r"((r)[20]), "=r"((r)[21]), "=r"((r)[22]), "=r"((r)[23]), \
          "=r"((r)[24]), "=r"((r)[25]), "=r"((r)[26]), "=r"((r)[27]), \
          "=r"((r)[28]), "=r"((r)[29]), "=r"((r)[30]), "=r"((r)[31]) \
        : "r"(ta))

__device__ __forceinline__ uint64_t make_desc(uint32_t addr) {
    const uint64_t base =
        (uint64_t(2)  << 61) | (uint64_t(1) << 46) | (uint64_t(64) << 32) | (uint64_t(1) << 16);
    return base | ((uint64_t)(addr >> 4) & 0x3FFF);
}

__device__ __forceinline__ void mma_tf32_ss(uint32_t d_tmem, uint64_t a_desc, uint64_t b_desc,
                                            uint32_t idesc, uint32_t enable) {
    asm volatile(
        "{\n\t"
        ".reg .pred p;\n\t"
        "setp.ne.u32 p, %4, 0;\n\t"
        "tcgen05.mma.cta_group::1.kind::tf32 [%0], %1, %2, %3, {%5, %5, %5, %5}, p;\n\t"
        "}"
        :: "r"(d_tmem), "l"(a_desc), "l"(b_desc), "r"(idesc), "r"(enable), "r"(0u)
        : "memory");
}

#define GEMM_IDESC ((1u << 4) | (2u << 7) | (2u << 10) | ((TN / 8) << 17) | ((TM / 16) << 24))

// Shared epilogue: TMEM -> smem (coalesce) -> gmem with bias
__device__ __forceinline__ void gemm_epilogue(char* smem, uint32_t tmem,
                                              const float* bsm, float* C,
                                              int bm0, int bn0, int tid)
{
    float* stg = (float*)(smem + SMEM_STAGE0);
    const int m = tid;
#pragma unroll 1
    for (int ch = 0; ch < 4; ch++) {
        uint32_t r[64];
        TC_LD_X32(r, tmem + ch * 64);
        TC_LD_X32(r + 32, tmem + ch * 64 + 32);
        TC_WAIT_LD();
        __syncthreads();
#pragma unroll
        for (int c = 0; c < 64; c++)
            stg[m * 65 + c] = __uint_as_float(r[c]) + bsm[ch * 64 + c];
        __syncthreads();
        size_t cb = (size_t)bm0 * DM + bn0 + ch * 64;
#pragma unroll 8
        for (int it = 0; it < 64; it++) {
            int i = tid + it * 128;
            int mm = i >> 6, cc = i & 63;
            C[cb + (size_t)mm * DM + cc] = stg[mm * 65 + cc];
        }
    }
}
#endif  // HAS_TC

// ============================================================
// Path A1 (preferred): TMA + mbarrier pipelined tcgen05 tf32 GEMM.
// One orchestrator thread; loads decoupled from MMA by NST stages.
// ============================================================
__global__ __launch_bounds__(128, 1)
void gemm_tma_kernel(const __grid_constant__ CUtensorMap mapA,
                     const __grid_constant__ CUtensorMap mapW,
                     const float* __restrict__ bias,
                     float* __restrict__ C)
{
#if HAS_TC
    extern __shared__ __align__(1024) char smem[];
    const uint32_t sb = smem_u32(smem);
    const int tid = threadIdx.x;
    const int wid = tid >> 5;
    const int bm0 = blockIdx.y * TM;
    const int bn0 = blockIdx.x * TN;

    // barriers: full[s] at sb+16+8s, empty[s] at sb+48+8s, done at sb+80
    const uint32_t FULL0 = sb + 16, EMPTY0 = sb + 48, DONE = sb + 80;

    float* bsm = (float*)(smem + 128);
    bsm[tid] = bias[bn0 + tid];
    bsm[tid + 128] = bias[bn0 + 128 + tid];

    if (wid == 0) TC_ALLOC(sb + 0, 256);
    if (tid == 0) {
        for (int s = 0; s < NST; s++) { MBAR_INIT(FULL0 + s * 8, 1); MBAR_INIT(EMPTY0 + s * 8, 1); }
        MBAR_INIT(DONE, 1);
    }
    __syncthreads();
    uint32_t tmem;
    asm volatile("ld.shared.b32 %0, [%1];" : "=r"(tmem) : "r"(sb + 0));

    if (tid == 0) {
        // prologue: issue loads for chunks 0..NST-2
#pragma unroll
        for (int j = 0; j < NST - 1; j++) {
            uint32_t ab = sb + SMEM_STAGE0 + j * STAGE_BYTES;
            MBAR_EXPECT_TX(FULL0 + j * 8, STAGE_BYTES);
            TMA_LD_2D(ab, &mapA, j * BK, bm0, FULL0 + j * 8);
            TMA_LD_2D(ab + A_STAGE_BYTES, &mapW, j * BK, bn0, FULL0 + j * 8);
        }
        for (int kc = 0; kc < NK; kc++) {
            const int j = kc + NST - 1;
            if (j < NK) {
                const int sl = j & (NST - 1);
                if (j >= NST) mbar_wait(EMPTY0 + sl * 8, ((j >> 2) - 1) & 1);
                uint32_t ab = sb + SMEM_STAGE0 + sl * STAGE_BYTES;
                MBAR_EXPECT_TX(FULL0 + sl * 8, STAGE_BYTES);
                TMA_LD_2D(ab, &mapA, j * BK, bm0, FULL0 + sl * 8);
                TMA_LD_2D(ab + A_STAGE_BYTES, &mapW, j * BK, bn0, FULL0 + sl * 8);
            }
            const int sl = kc & (NST - 1);
            mbar_wait(FULL0 + sl * 8, (kc >> 2) & 1);
            uint32_t ab = sb + SMEM_STAGE0 + sl * STAGE_BYTES;
            uint64_t ad = make_desc(ab);
            uint64_t bd = make_desc(ab + A_STAGE_BYTES);
#pragma unroll
            for (int t = 0; t < 4; t++)
                mma_tf32_ss(tmem, ad + t * 2, bd + t * 2, GEMM_IDESC, (uint32_t)((kc | t) != 0));
            TC_COMMIT(EMPTY0 + sl * 8);
        }
        TC_COMMIT(DONE);
    }
    mbar_wait(DONE, 0);
    TC_FENCE_AFTER();

    gemm_epilogue(smem, tmem, bsm, C, bm0, bn0, tid);

    __syncthreads();
    if (wid == 0) { TC_RELINQ(); TC_DEALLOC(tmem, 256); }
#else
    (void)bias; (void)C;
#endif
}

// ============================================================
// Path A2 (fallback if tensormap encode unavailable): proven cp.async GEMM
// ============================================================
__global__ __launch_bounds__(128, 1)
void gemm_tf32_kernel(const float* __restrict__ A,
                      const float* __restrict__ W,
                      const float* __restrict__ bias,
                      float* __restrict__ C)
{
#if HAS_TC
    extern __shared__ __align__(1024) char smem[];
    const uint32_t sb = smem_u32(smem);
    const int tid = threadIdx.x;
    const int wid = tid >> 5;
    const int bm0 = blockIdx.y * TM;
    const int bn0 = blockIdx.x * TN;

    float* bsm = (float*)(smem + 128);
    bsm[tid] = bias[bn0 + tid];
    bsm[tid + 128] = bias[bn0 + 128 + tid];

    if (wid == 0) TC_ALLOC(sb + 0, 256);
    if (tid == 0) {
        for (int s = 0; s < NST; s++) MBAR_INIT(sb + 16 + s * 8, 1);
        MBAR_INIT(sb + 16 + NST * 8, 1);
    }
    __syncthreads();
    uint32_t tmem;
    asm volatile("ld.shared.b32 %0, [%1];" : "=r"(tmem) : "r"(sb + 0));

    const float* Abase = A + (size_t)bm0 * DM;
    const float* Wbase = W + (size_t)bn0 * DM;

#pragma unroll
    for (int j = 0; j < NST - 1; j++) {
        uint32_t abase = sb + SMEM_STAGE0 + j * STAGE_BYTES;
        uint32_t bbase = abase + A_STAGE_BYTES;
#pragma unroll
        for (int r = 0; r < 8; r++) {
            int i = tid + r * 128; int row = i >> 3, c16 = i & 7;
            CP_ASYNC16(abase + SWZ(row * 128 + c16 * 16),
                       Abase + (size_t)row * DM + j * BK + c16 * 4);
        }
#pragma unroll
        for (int r = 0; r < 16; r++) {
            int i = tid + r * 128; int row = i >> 3, c16 = i & 7;
            CP_ASYNC16(bbase + SWZ(row * 128 + c16 * 16),
                       Wbase + (size_t)row * DM + j * BK + c16 * 4);
        }
        CP_COMMIT();
    }

    for (int kc = 0; kc < NK; kc++) {
        const int j = kc + NST - 1;
        if (j < NK) {
            const int sl = j & (NST - 1);
            if (j >= NST) mbar_wait(sb + 16 + sl * 8, ((j >> 2) - 1) & 1);
            uint32_t abase = sb + SMEM_STAGE0 + sl * STAGE_BYTES;
            uint32_t bbase = abase + A_STAGE_BYTES;
#pragma unroll
            for (int r = 0; r < 8; r++) {
                int i = tid + r * 128; int row = i >> 3, c16 = i & 7;
                CP_ASYNC16(abase + SWZ(row * 128 + c16 * 16),
                           Abase + (size_t)row * DM + j * BK + c16 * 4);
            }
#pragma unroll
            for (int r = 0; r < 16; r++) {
                int i = tid + r * 128; int row = i >> 3, c16 = i & 7;
                CP_ASYNC16(bbase + SWZ(row * 128 + c16 * 16),
                           Wbase + (size_t)row * DM + j * BK + c16 * 4);
            }
        }
        CP_COMMIT();
        CP_WAIT3();
        __syncthreads();
        if (tid == 0) {
            FENCE_PROXY();
            const int sl = kc & (NST - 1);
            uint32_t abase = sb + SMEM_STAGE0 + sl * STAGE_BYTES;
            uint64_t ad = make_desc(abase);
            uint64_t bd = make_desc(abase + A_STAGE_BYTES);
#pragma unroll
            for (int t = 0; t < 4; t++)
                mma_tf32_ss(tmem, ad + t * 2, bd + t * 2, GEMM_IDESC, (uint32_t)((kc | t) != 0));
            TC_COMMIT(sb + 16 + sl * 8);
        }
    }
    if (tid == 0) TC_COMMIT(sb + 16 + NST * 8);
    mbar_wait(sb + 16 + NST * 8, 0);
    TC_FENCE_AFTER();

    gemm_epilogue(smem, tmem, bsm, C, bm0, bn0, tid);

    __syncthreads();
    if (wid == 0) { TC_RELINQ(); TC_DEALLOC(tmem, 256); }
#else
    (void)A; (void)W; (void)bias; (void)C;
#endif
}

// ============================================================
// Path B: mma.sync tf32 fallback GEMM (empty when tcgen05 available)
// ============================================================
__global__ __launch_bounds__(256, 1)
void gemm_mma_kernel(const float* __restrict__ A,
                     const float* __restrict__ W,
                     const float* __restrict__ bias,
                     float* __restrict__ C)
{
#if defined(__CUDA_ARCH__) && !HAS_TC
    extern __shared__ __align__(16) float fsm[];
    float* As = fsm;
    float* Bs = fsm + 2 * 128 * 36;
    const uint32_t as_u = smem_u32(As);
    const uint32_t bs_u = smem_u32(Bs);

    const int tid = threadIdx.x;
    const int lane = tid & 31, warp = tid >> 5;
    const int wm = warp & 3;
    const int wn = warp >> 2;
    const int g = lane >> 2, ti = lane & 3;
    const int bm0 = blockIdx.y * 128;
    const int bn0 = blockIdx.x * 128;

    const float* Ag = A + (size_t)bm0 * DM;
    const float* Wg = W + (size_t)bn0 * DM;

    float c[2][8][4];
#pragma unroll
    for (int mi = 0; mi < 2; mi++)
#pragma unroll
        for (int ni = 0; ni < 8; ni++)
#pragma unroll
            for (int q = 0; q < 4; q++) c[mi][ni][q] = 0.f;

    auto load = [&](int st, int kc) {
        uint32_t ab = as_u + st * (128 * 36 * 4);
        uint32_t bb = bs_u + st * (128 * 36 * 4);
        const float* Ak = Ag + kc * 32;
        const float* Wk = Wg + kc * 32;
#pragma unroll
        for (int r = 0; r < 4; r++) {
            int i = tid + r * 256; int row = i >> 3, cc = i & 7;
            CP_ASYNC16(ab + row * 144 + cc * 16, Ak + (size_t)row * DM + cc * 4);
            CP_ASYNC16(bb + row * 144 + cc * 16, Wk + (size_t)row * DM + cc * 4);
        }
    };

    load(0, 0); CP_COMMIT();
    for (int kc = 0; kc < DM / 32; kc++) {
        if (kc + 1 < DM / 32) load((kc + 1) & 1, kc + 1);
        CP_COMMIT();
        CP_WAIT1();
        __syncthreads();
        const float* as_ = As + (kc & 1) * 128 * 36;
        const float* bs_ = Bs + (kc & 1) * 128 * 36;
#pragma unroll
        for (int ks = 0; ks < 4; ks++) {
            uint32_t a[2][4], b[8][2];
#pragma unroll
            for (int mi = 0; mi < 2; mi++) {
                int r0 = wm * 32 + mi * 16 + g;
                a[mi][0] = __float_as_uint(as_[r0 * 36 + ks * 8 + ti]);
                a[mi][1] = __float_as_uint(as_[(r0 + 8) * 36 + ks * 8 + ti]);
                a[mi][2] = __float_as_uint(as_[r0 * 36 + ks * 8 + ti + 4]);
                a[mi][3] = __float_as_uint(as_[(r0 + 8) * 36 + ks * 8 + ti + 4]);
            }
#pragma unroll
            for (int ni = 0; ni < 8; ni++) {
                int n0 = wn * 64 + ni * 8 + g;
                b[ni][0] = __float_as_uint(bs_[n0 * 36 + ks * 8 + ti]);
                b[ni][1] = __float_as_uint(bs_[n0 * 36 + ks * 8 + ti + 4]);
            }
#pragma unroll
            for (int mi = 0; mi < 2; mi++)
#pragma unroll
                for (int ni = 0; ni < 8; ni++)
                    MMA_TF32(c[mi][ni], a[mi], b[ni]);
        }
        __syncthreads();
    }

#pragma unroll
    for (int mi = 0; mi < 2; mi++) {
        int r0 = bm0 + wm * 32 + mi * 16 + g;
#pragma unroll
        for (int ni = 0; ni < 8; ni++) {
            int c0 = bn0 + wn * 64 + ni * 8 + ti * 2;
            float b0 = bias[c0], b1 = bias[c0 + 1];
            C[(size_t)r0 * DM + c0]           = c[mi][ni][0] + b0;
            C[(size_t)r0 * DM + c0 + 1]       = c[mi][ni][1] + b1;
            C[(size_t)(r0 + 8) * DM + c0]     = c[mi][ni][2] + b0;
            C[(size_t)(r0 + 8) * DM + c0 + 1] = c[mi][ni][3] + b1;
        }
    }
#else
    (void)A; (void)W; (void)bias; (void)C;
#endif
}

// ============================================================
// Round fp32 -> tf32 (RN), vectorized (weights only)
// ============================================================
__global__ void round_tf32_kernel(const float4* __restrict__ x, float4* __restrict__ y)
{
    int i = blockIdx.x * blockDim.x + threadIdx.x;
    float4 v = x[i];
    v.x = rtf(v.x); v.y = rtf(v.y); v.z = rtf(v.z); v.w = rtf(v.w);
    y[i] = v;
}

// ============================================================
// Fused KV accumulation with inline depthwise conv + fmap.
// ============================================================
__global__ __launch_bounds__(256)
void kv_accum_kernel(const float* __restrict__ pk, const float* __restrict__ pv,
                     const float* __restrict__ kcw, const float* __restrict__ kcb,
                     const float* __restrict__ vcw, const float* __restrict__ vcb)
{
    const int bh = blockIdx.x;
    const int b = bh / HH, h = bh % HH;
    const int split = blockIdx.y;

    __shared__ float Pk[34 * 64], Pv[34 * 64];
    __shared__ float Ks[32][64], Vs[32][64];
    __shared__ float Wk[192], Bk[64], Wv[192], Bv[64];

    const int t = threadIdx.x;
    if (t < 192) { Wk[t] = kcw[t]; Wv[t] = vcw[t]; }
    if (t < 64)  { Bk[t] = kcb[t]; Bv[t] = vcb[t]; }

    const int d = t >> 2;
    const int e0 = t & 3;

    float acc[16];
#pragma unroll
    for (int j = 0; j < 16; j++) acc[j] = 0.f;
    float ksum = 0.f;

    const size_t base = (size_t)b * SS * DM + h * HD;
    const int sbeg = split * (SS / NSPLIT);

    for (int s0 = sbeg; s0 < sbeg + SS / NSPLIT; s0 += 32) {
#pragma unroll
        for (int r = 0; r < 9; r++) {
            int li = r * 256 + t;
            if (li < 34 * 64) {
                int lr = li >> 6, ld = li & 63;
                int s = s0 - 2 + lr;
                float kv_ = 0.f, vv_ = 0.f;
                if (s >= 0) {
                    size_t g = base + (size_t)s * DM + ld;
                    kv_ = pk[g]; vv_ = pv[g];
                }
                Pk[li] = kv_; Pv[li] = vv_;
            }
        }
        __syncthreads();
#pragma unroll
        for (int r = 0; r < 8; r++) {
            int li = r * 256 + t;
            int lr = li >> 6, ld = li & 63;
            float kk = Bk[ld] + Wk[ld*3+2]*Pk[(lr+2)*64+ld]
                              + Wk[ld*3+1]*Pk[(lr+1)*64+ld]
                              + Wk[ld*3+0]*Pk[lr*64+ld];
            Ks[lr][ld] = (kk > 0.f) ? (kk + 1.f) : expf(kk);
            float vv = Bv[ld] + Wv[ld*3+2]*Pv[(lr+2)*64+ld]
                              + Wv[ld*3+1]*Pv[(lr+1)*64+ld]
                              + Wv[ld*3+0]*Pv[lr*64+ld];
            Vs[lr][ld] = vv;
        }
        __syncthreads();
#pragma unroll 4
        for (int s = 0; s < 32; s++) {
            float kd = Ks[s][d];
            ksum += kd;
#pragma unroll
            for (int j = 0; j < 16; j++)
                acc[j] += kd * Vs[s][e0 + 4 * j];
        }
        __syncthreads();
    }

    float* kvout = g_KVpart + (((size_t)split * NBH + bh) * HD + d) * HD;
#pragma unroll
    for (int j = 0; j < 16; j++) kvout[e0 + 4 * j] = acc[j];
    if (e0 == 0) g_Ksump[((size_t)split * NBH + bh) * HD + d] = ksum;
}

__global__ void kv_reduce_kernel()
{
    int i = blockIdx.x * blockDim.x + threadIdx.x;
    float s = 0.f;
#pragma unroll
    for (int p = 0; p < NSPLIT; p++) s += g_KVpart[(size_t)p * NBH * HD * HD + i];
    g_KV[i] = s;
    if (i < NBH * HD) {
        float s2 = 0.f;
#pragma unroll
        for (int p = 0; p < NSPLIT; p++) s2 += g_Ksump[p * NBH * HD + i];
        g_Ksum[i] = s2;
    }
}

// ============================================================
// V_new with inline conv+fmap on raw Q projection; tf32-rounded output.
// ============================================================
__global__ __launch_bounds__(256)
void vnew_kernel(const float* __restrict__ pq, float* __restrict__ out,
                 const float* __restrict__ qcw, const float* __restrict__ qcb)
{
    const int bh = blockIdx.x;
    const int b = bh / HH, h = bh % HH;
    const int s0 = blockIdx.y * 32;

    __shared__ float KVs[64 * 64];
    __shared__ float Kss[64];
    __shared__ float Pq[34 * 64];
    __shared__ float Qs[32][64];
    __shared__ float Wq[192], Bq[64];

    const int t = threadIdx.x;
    if (t < 192) Wq[t] = qcw[t];
    if (t < 64)  Bq[t] = qcb[t];

    const float* kvsrc = g_KV + (size_t)bh * HD * HD;
#pragma unroll
    for (int r = 0; r < 16; r++) KVs[r * 256 + t] = kvsrc[r * 256 + t];
    if (t < 64) Kss[t] = g_Ksum[bh * HD + t] + EPS;

    const size_t base = (size_t)b * SS * DM + h * HD;
#pragma unroll
    for (int r = 0; r < 9; r++) {
        int li = r * 256 + t;
        if (li < 34 * 64) {
            int lr = li >> 6, ld = li & 63;
            int s = s0 - 2 + lr;
            Pq[li] = (s >= 0) ? pq[base + (size_t)s * DM + ld] : 0.f;
        }
    }
    __syncthreads();
#pragma unroll
    for (int r = 0; r < 8; r++) {
        int li = r * 256 + t;
        int lr = li >> 6, ld = li & 63;
        float q = Bq[ld] + Wq[ld*3+2]*Pq[(lr+2)*64+ld]
                         + Wq[ld*3+1]*Pq[(lr+1)*64+ld]
                         + Wq[ld*3+0]*Pq[lr*64+ld];
        Qs[lr][ld] = (q > 0.f) ? (q + 1.f) : expf(q);
    }
    __syncthreads();

    const int sl = t >> 3;
    const int e0 = (t & 7) * 8;

    float denom = 0.f;
#pragma unroll
    for (int dd = 0; dd < 64; dd++) denom += Qs[sl][dd] * Kss[dd];
    float zinv = 1.f / denom;

    float acc[8];
#pragma unroll
    for (int j = 0; j < 8; j++) acc[j] = 0.f;
#pragma unroll
    for (int dd = 0; dd < 64; dd++) {
        float qd = Qs[sl][dd];
#pragma unroll
        for (int j = 0; j < 8; j++) acc[j] += KVs[dd * 64 + e0 + j] * qd;
    }

    size_t ob = base + (size_t)(s0 + sl) * DM + e0;
#pragma unroll
    for (int j = 0; j < 8; j++) out[ob + j] = rtf(acc[j] * zinv);
}

// ============================================================
// Host: tensormap creation via driver entry point (no -lcuda needed)
// ============================================================
typedef CUresult (*EncodeTiledFn)(CUtensorMap*, CUtensorMapDataType, cuuint32_t, void*,
                                  const cuuint64_t*, const cuuint64_t*,
                                  const cuuint32_t*, const cuuint32_t*,
                                  CUtensorMapInterleave, CUtensorMapSwizzle,
                                  CUtensorMapL2promotion, CUtensorMapFloatOOBfill);

static bool make_map2d(EncodeTiledFn enc, CUtensorMap* m, const float* ptr,
                       uint64_t rows, uint32_t boxRows)
{
    cuuint64_t dims[2]    = {DM, rows};
    cuuint64_t strides[1] = {DM * sizeof(float)};
    cuuint32_t box[2]     = {BK, boxRows};
    cuuint32_t es[2]      = {1, 1};
    return enc(m, CU_TENSOR_MAP_DATA_TYPE_FLOAT32, 2, (void*)ptr,
               dims, strides, box, es,
               CU_TENSOR_MAP_INTERLEAVE_NONE, CU_TENSOR_MAP_SWIZZLE_128B,
               CU_TENSOR_MAP_L2_PROMOTION_L2_128B,
               CU_TENSOR_MAP_FLOAT_OOB_FILL_NONE) == CUDA_SUCCESS;
}

extern "C" void kernel_launch(void* const* d_in, const int* in_sizes, int n_in,
                              void* d_out, int out_size)
{
    const float* query = (const float*)d_in[0];
    const float* key   = (const float*)d_in[1];
    const float* value = (const float*)d_in[2];
    const float* q_w   = (const float*)d_in[3];
    const float* q_b   = (const float*)d_in[4];
    const float* k_w   = (const float*)d_in[5];
    const float* k_b   = (const float*)d_in[6];
    const float* v_w   = (const float*)d_in[7];
    const float* v_b   = (const float*)d_in[8];
    const float* o_w   = (const float*)d_in[9];
    const float* o_b   = (const float*)d_in[10];
    const float* qc_w  = (const float*)d_in[11];
    const float* qc_b  = (const float*)d_in[12];
    const float* kc_w  = (const float*)d_in[13];
    const float* kc_b  = (const float*)d_in[14];
    const float* vc_w  = (const float*)d_in[15];
    const float* vc_b  = (const float*)d_in[16];
    float* out = (float*)d_out;

    float *proj, *vnew, *rw;
    cudaGetSymbolAddress((void**)&proj, g_proj);
    cudaGetSymbolAddress((void**)&vnew, g_vnew);
    cudaGetSymbolAddress((void**)&rw,   g_rw);
    float* pq = proj;  float* pk = proj + (size_t)NEL;  float* pv = proj + 2 * (size_t)NEL;
    float* rqw = rw;                       float* rkw = rw + (size_t)DM * DM;
    float* rvw = rw + 2 * (size_t)DM * DM; float* row_ = rw + 3 * (size_t)DM * DM;

    cudaFuncSetAttribute(gemm_tma_kernel,
                         cudaFuncAttributeMaxDynamicSharedMemorySize, GEMM_SMEM);
    cudaFuncSetAttribute(gemm_tf32_kernel,
                         cudaFuncAttributeMaxDynamicSharedMemorySize, GEMM_SMEM);
    cudaFuncSetAttribute(gemm_mma_kernel,
                         cudaFuncAttributeMaxDynamicSharedMemorySize, MMA_SMEM);

    // driver entry point for cuTensorMapEncodeTiled (avoids -lcuda link dep)
    EncodeTiledFn enc = nullptr;
    {
        void* p = nullptr;
        cudaDriverEntryPointQueryResult qr;
        if (cudaGetDriverEntryPoint("cuTensorMapEncodeTiled", &p,
                                    cudaEnableDefault, &qr) == cudaSuccess && p)
            enc = (EncodeTiledFn)p;
    }

    CUtensorMap mAq{}, mAk{}, mAv{}, mAo{}, mWq{}, mWk{}, mWv{}, mWo{};
    bool use_tma = (enc != nullptr);
    if (use_tma) {
        use_tma = make_map2d(enc, &mAq, query, MTOT, TM)
               && make_map2d(enc, &mAk, key,   MTOT, TM)
               && make_map2d(enc, &mAv, value, MTOT, TM)
               && make_map2d(enc, &mAo, vnew,  MTOT, TM)
               && make_map2d(enc, &mWq, rqw,  DM, TN)
               && make_map2d(enc, &mWk, rkw,  DM, TN)
               && make_map2d(enc, &mWv, rvw,  DM, TN)
               && make_map2d(enc, &mWo, row_, DM, TN);
    }

    const int WN4 = (DM * DM) / 4;

    // 0) round weights to tf32 (RN)
    round_tf32_kernel<<<WN4 / 256, 256>>>((const float4*)q_w, (float4*)rqw);
    round_tf32_kernel<<<WN4 / 256, 256>>>((const float4*)k_w, (float4*)rkw);
    round_tf32_kernel<<<WN4 / 256, 256>>>((const float4*)v_w, (float4*)rvw);
    round_tf32_kernel<<<WN4 / 256, 256>>>((const float4*)o_w, (float4*)row_);

    dim3 ggrid_tc(DM / TN, MTOT / TM);    // (4, 128)
    dim3 ggrid_mma(DM / 128, MTOT / 128); // (8, 128)

#define LAUNCH_GEMM(MA, MW, Araw, Wr, Bias, Cout) do { \
        gemm_mma_kernel<<<ggrid_mma, 256, MMA_SMEM>>>(Araw, Wr, Bias, Cout); \
        if (use_tma) \
            gemm_tma_kernel<<<ggrid_tc, 128, GEMM_SMEM>>>(MA, MW, Bias, Cout); \
        else \
            gemm_tf32_kernel<<<ggrid_tc, 128, GEMM_SMEM>>>(Araw, Wr, Bias, Cout); \
    } while (0)

    // 1) QKV projections on RAW inputs (tf32 truncation inside MMA)
    LAUNCH_GEMM(mAq, mWq, query, rqw, q_b, pq);
    LAUNCH_GEMM(mAk, mWk, key,   rkw, k_b, pk);
    LAUNCH_GEMM(mAv, mWv, value, rvw, v_b, pv);

    // 2) KV = conv_k(K)^T conv_v(V) and Ksum (conv fused)
    kv_accum_kernel<<<dim3(NBH, NSPLIT), 256>>>(pk, pv, kc_w, kc_b, vc_w, vc_b);
    kv_reduce_kernel<<<(NBH * HD * HD) / 256, 256>>>();

    // 3) V_new (conv_q fused, tf32-rounded output)
    vnew_kernel<<<dim3(NBH, SS / 32), 256>>>(pq, vnew, qc_w, qc_b);

    // 4) output projection
    LAUNCH_GEMM(mAo, mWo, vnew, row_, o_b, out);
#undef LAUNCH_GEMM
}

// round 11
// speedup vs baseline: 1.8343x; 1.1343x over previous
#include <cuda_runtime.h>
#include <cuda.h>
#include <math.h>
#include <stdint.h>

// Problem constants
#define BB 4
#define SS 4096
#define DM 1024
#define HH 16
#define HD 64
#define MTOT (BB*SS)            // 16384
#define NEL (MTOT*DM)           // 16,777,216
#define EPS 1e-6f
#define NBH (BB*HH)             // 64
#define NSPLIT 8

// ---- arch-feature detection ----
#if defined(__CUDA_ARCH_FEAT_SM103_ALL) || defined(__CUDA_ARCH_FEAT_SM100_ALL) || \
    (defined(__CUDA_ARCH_SPECIFIC__) && (__CUDA_ARCH_SPECIFIC__ == 1030 || __CUDA_ARCH_SPECIFIC__ == 1000)) || \
    (defined(__CUDA_ARCH_FAMILY_SPECIFIC__) && (__CUDA_ARCH_FAMILY_SPECIFIC__ == 1030 || __CUDA_ARCH_FAMILY_SPECIFIC__ == 1000))
#define HAS_TC 1
#else
#define HAS_TC 0
#endif

// tcgen05 GEMM tiling
#define TM 128
#define TN 256
#define BK 32                   // floats per k-chunk = 128 B (one SW128 row)
#define NK (DM/BK)              // 32
#define NST 4
#define A_STAGE_BYTES (TM*128)  // 16 KB
#define B_STAGE_BYTES (TN*128)  // 32 KB
#define STAGE_BYTES (A_STAGE_BYTES + B_STAGE_BYTES)   // 48 KB
#define SMEM_STAGE0 2048
#define GEMM_SMEM (SMEM_STAGE0 + NST*STAGE_BYTES)     // 198656 (non-persistent fallback)

// persistent kernel
#define NTILES 4
#define GRID_P 128
#define NKTOT (NTILES*NK)       // 128 chunks
#define EPI_STG_OFF (SMEM_STAGE0 + NST*STAGE_BYTES)   // 198656
#define EPI_STG_BYTES (64*65*4)                       // 16640
#define PSMEM (EPI_STG_OFF + EPI_STG_BYTES)           // 215296

// mma.sync fallback tiling
#define MMA_SMEM (4*128*36*4)

// -------- scratch --------
__device__ float g_proj[3 * NEL];
__device__ float g_vnew[NEL];
__device__ float g_rw[4 * DM * DM];
__device__ float g_KVpart[NSPLIT * NBH * HD * HD];
__device__ float g_Ksump[NSPLIT * NBH * HD];
__device__ float g_KV[NBH * HD * HD];
__device__ float g_Ksum[NBH * HD];

// ============================================================
// PTX helpers
// ============================================================
__device__ __forceinline__ uint32_t smem_u32(const void* p) {
    uint32_t a;
    asm("{ .reg .u64 t; cvta.to.shared.u64 t, %1; cvt.u32.u64 %0, t; }" : "=r"(a) : "l"(p));
    return a;
}
#define SWZ(o) ((o) ^ (((o) >> 3) & 0x70))

#define CP_ASYNC16(dst, src) \
    asm volatile("cp.async.cg.shared.global [%0], [%1], 16;" :: "r"(dst), "l"(src) : "memory")
#define CP_COMMIT() asm volatile("cp.async.commit_group;" ::: "memory")
#define CP_WAIT3()  asm volatile("cp.async.wait_group 3;" ::: "memory")
#define CP_WAIT1()  asm volatile("cp.async.wait_group 1;" ::: "memory")

#define MBAR_INIT(addr, cnt) \
    asm volatile("mbarrier.init.shared.b64 [%0], %1;" :: "r"(addr), "r"(cnt) : "memory")
#define MBAR_EXPECT_TX(addr, bytes) \
    asm volatile("mbarrier.arrive.expect_tx.shared.b64 _, [%0], %1;" :: "r"(addr), "r"(bytes) : "memory")
#define MBAR_ARRIVE(addr) \
    asm volatile("mbarrier.arrive.shared.b64 _, [%0];" :: "r"(addr) : "memory")
__device__ __forceinline__ void mbar_wait(uint32_t addr, uint32_t phase) {
    asm volatile(
        "{\n\t.reg .pred P;\n\t"
        "W_%=:\n\t"
        "mbarrier.try_wait.parity.shared.b64 P, [%0], %1, 0x989680;\n\t"
        "@P bra D_%=;\n\t"
        "bra W_%=;\n\t"
        "D_%=:\n\t}"
        :: "r"(addr), "r"(phase) : "memory");
}
#define BAR1_128() asm volatile("bar.sync 1, 128;" ::: "memory")

__device__ __forceinline__ float rtf(float x) {
    asm("cvt.rna.tf32.f32 %0, %0;" : "+f"(x));
    return x;
}

#define MMA_TF32(c, a, b) \
    asm volatile("mma.sync.aligned.m16n8k8.row.col.f32.tf32.tf32.f32 " \
        "{%0,%1,%2,%3}, {%4,%5,%6,%7}, {%8,%9}, {%0,%1,%2,%3};" \
        : "+f"((c)[0]), "+f"((c)[1]), "+f"((c)[2]), "+f"((c)[3]) \
        : "r"((a)[0]), "r"((a)[1]), "r"((a)[2]), "r"((a)[3]), \
          "r"((b)[0]), "r"((b)[1]))

#if HAS_TC
#define TC_ALLOC(sm, n)   asm volatile("tcgen05.alloc.cta_group::1.sync.aligned.shared::cta.b32 [%0], %1;" :: "r"(sm), "r"(n) : "memory")
#define TC_DEALLOC(t, n)  asm volatile("tcgen05.dealloc.cta_group::1.sync.aligned.b32 %0, %1;" :: "r"(t), "r"(n))
#define TC_RELINQ()       asm volatile("tcgen05.relinquish_alloc_permit.cta_group::1.sync.aligned;")
#define TC_COMMIT(mb)     asm volatile("tcgen05.commit.cta_group::1.mbarrier::arrive::one.shared::cluster.b64 [%0];" :: "r"(mb) : "memory")
#define TC_FENCE_AFTER()  asm volatile("tcgen05.fence::after_thread_sync;" ::: "memory")
#define TC_WAIT_LD()      asm volatile("tcgen05.wait::ld.sync.aligned;" ::: "memory")
#define FENCE_PROXY()     asm volatile("fence.proxy.async.shared::cta;" ::: "memory")

#define TMA_LD_2D(smem, map, x, y, mb) \
    asm volatile("cp.async.bulk.tensor.2d.shared::cta.global.tile.mbarrier::complete_tx::bytes " \
        "[%0], [%1, {%2, %3}], [%4];" \
        :: "r"(smem), "l"(map), "r"(x), "r"(y), "r"(mb) : "memory")

#define TC_LD_X32(r, ta) \
    asm volatile( \
        "tcgen05.ld.sync.aligned.32x32b.x32.b32 " \
        "{%0, %1, %2, %3, %4, %5, %6, %7, " \
        " %8, %9, %10, %11, %12, %13, %14, %15, " \
        " %16, %17, %18, %19, %20, %21, %22, %23, " \
        " %24, %25, %26, %27, %28, %29, %30, %31}, [%32];" \
        : "=r"((r)[0]),  "=r"((r)[1]),  "=r"((r)[2]),  "=r"((r)[3]), \
          "=r"((r)[4]),  "=r"((r)[5]),  "=r"((r)[6]),  "=r"((r)[7]), \
          "=r"((r)[8]),  "=r"((r)[9]),  "=r"((r)[10]), "=r"((r)[11]), \
          "=r"((r)[12]), "=r"((r)[13]), "=r"((r)[14]), "=r"((r)[15]), \
          "=r"((r)[16]), "=r"((r)[17]), "=r"((r)[18]), "=r"((r)[19]), \
          "=r"((r)[20]), "=r"((r)[21]), "=r"((r)[22]), "=r"((r)[23]), \
          "=r"((r)[24]), "=r"((r)[25]), "=r"((r)[26]), "=r"((r)[27]), \
          "=r"((r)[28]), "=r"((r)[29]), "=r"((r)[30]), "=r"((r)[31]) \
        : "r"(ta))

__device__ __forceinline__ uint64_t make_desc(uint32_t addr) {
    const uint64_t base =
        (uint64_t(2)  << 61) | (uint64_t(1) << 46) | (uint64_t(64) << 32) | (uint64_t(1) << 16);
    return base | ((uint64_t)(addr >> 4) & 0x3FFF);
}

__device__ __forceinline__ void mma_tf32_ss(uint32_t d_tmem, uint64_t a_desc, uint64_t b_desc,
                                            uint32_t idesc, uint32_t enable) {
    asm volatile(
        "{\n\t"
        ".reg .pred p;\n\t"
        "setp.ne.u32 p, %4, 0;\n\t"
        "tcgen05.mma.cta_group::1.kind::tf32 [%0], %1, %2, %3, {%5, %5, %5, %5}, p;\n\t"
        "}"
        :: "r"(d_tmem), "l"(a_desc), "l"(b_desc), "r"(idesc), "r"(enable), "r"(0u)
        : "memory");
}

#define GEMM_IDESC ((1u << 4) | (2u << 7) | (2u << 10) | ((TN / 8) << 17) | ((TM / 16) << 24))
#endif  // HAS_TC

// ============================================================
// Persistent TMA + double-buffered-TMEM tcgen05 GEMM.
// 128 CTAs x 4 M-tiles; fixed N-column per CTA. 160 threads:
// warps 0-3 = epilogue workers, warp 4 lane 0 = orchestrator.
// Barriers: full[s]@16+8s, empty[s]@48+8s, mmadone[b]@80+8b, epifree[b]@96+8b
// ============================================================
__global__ __launch_bounds__(160, 1)
void gemm_persist_kernel(const __grid_constant__ CUtensorMap mapA,
                         const __grid_constant__ CUtensorMap mapW,
                         const float* __restrict__ bias,
                         float* __restrict__ C)
{
#if HAS_TC
    extern __shared__ __align__(1024) char smem[];
    const uint32_t sb = smem_u32(smem);
    const int tid = threadIdx.x;
    const int wid = tid >> 5;
    const int bn0 = (blockIdx.x & 3) * TN;
    const int bmBase = (blockIdx.x >> 2) * NTILES;   // tile t -> bm0=(bmBase+t)*TM

    float* bsm = (float*)(smem + 128);
    if (tid < 128) { bsm[tid] = bias[bn0 + tid]; bsm[tid + 128] = bias[bn0 + 128 + tid]; }

    if (wid == 0) TC_ALLOC(sb, 512);
    if (tid == 0) {
        for (int s = 0; s < NST; s++) { MBAR_INIT(sb + 16 + s * 8, 1); MBAR_INIT(sb + 48 + s * 8, 1); }
        MBAR_INIT(sb + 80, 1); MBAR_INIT(sb + 88, 1);
        MBAR_INIT(sb + 96, 1); MBAR_INIT(sb + 104, 1);
    }
    __syncthreads();
    uint32_t tmem;
    asm volatile("ld.shared.b32 %0, [%1];" : "=r"(tmem) : "r"(sb));

    if (tid == 128) {
        // ---- orchestrator: flat chunk stream across all 4 tiles ----
#pragma unroll
        for (int j = 0; j < NST - 1; j++) {
            uint32_t ab = sb + SMEM_STAGE0 + j * STAGE_BYTES;
            MBAR_EXPECT_TX(sb + 16 + j * 8, STAGE_BYTES);
            TMA_LD_2D(ab, &mapA, (j & 31) * BK, (bmBase + (j >> 5)) * TM, sb + 16 + j * 8);
            TMA_LD_2D(ab + A_STAGE_BYTES, &mapW, (j & 31) * BK, bn0, sb + 16 + j * 8);
        }
        for (int c = 0; c < NKTOT; c++) {
            const int j = c + NST - 1;
            if (j < NKTOT) {
                const int sl = j & 3;
                if (j >= NST) mbar_wait(sb + 48 + sl * 8, ((j >> 2) - 1) & 1);
                uint32_t ab = sb + SMEM_STAGE0 + sl * STAGE_BYTES;
                MBAR_EXPECT_TX(sb + 16 + sl * 8, STAGE_BYTES);
                TMA_LD_2D(ab, &mapA, (j & 31) * BK, (bmBase + (j >> 5)) * TM, sb + 16 + sl * 8);
                TMA_LD_2D(ab + A_STAGE_BYTES, &mapW, (j & 31) * BK, bn0, sb + 16 + sl * 8);
            }
            const int sl = c & 3, kc = c & 31, tc = c >> 5, buf = tc & 1;
            mbar_wait(sb + 16 + sl * 8, (c >> 2) & 1);
            if (kc == 0 && tc >= 2) mbar_wait(sb + 96 + buf * 8, 0);  // epilogue of tile tc-2 done
            uint32_t ab = sb + SMEM_STAGE0 + sl * STAGE_BYTES;
            uint64_t ad = make_desc(ab);
            uint64_t bd = make_desc(ab + A_STAGE_BYTES);
            uint32_t dt = tmem + buf * 256;
#pragma unroll
            for (int t4 = 0; t4 < 4; t4++)
                mma_tf32_ss(dt, ad + t4 * 2, bd + t4 * 2, GEMM_IDESC, (uint32_t)((kc | t4) != 0));
            TC_COMMIT(sb + 48 + sl * 8);
            if (kc == NK - 1) TC_COMMIT(sb + 80 + buf * 8);
        }
    } else if (tid < 128) {
        // ---- epilogue workers ----
        float* stg = (float*)(smem + EPI_STG_OFF);
#pragma unroll 1
        for (int t = 0; t < NTILES; t++) {
            const int buf = t & 1;
            mbar_wait(sb + 80 + buf * 8, (t >> 1) & 1);
            TC_FENCE_AFTER();
            const int bm0 = (bmBase + t) * TM;
            const uint32_t dt = tmem + buf * 256;
#pragma unroll 1
            for (int ch = 0; ch < 4; ch++) {
                uint32_t r[64];
                TC_LD_X32(r, dt + ch * 64);
                TC_LD_X32(r + 32, dt + ch * 64 + 32);
                TC_WAIT_LD();
#pragma unroll 1
                for (int p = 0; p < 2; p++) {
                    BAR1_128();
                    if ((tid >> 6) == p) {
                        int m = tid & 63;
#pragma unroll
                        for (int cc = 0; cc < 64; cc++)
                            stg[m * 65 + cc] = __uint_as_float(r[cc]) + bsm[ch * 64 + cc];
                    }
                    BAR1_128();
                    size_t cb = (size_t)(bm0 + p * 64) * DM + bn0 + ch * 64;
#pragma unroll 8
                    for (int it = 0; it < 32; it++) {
                        int i = tid + it * 128;
                        int mm = i >> 6, cc = i & 63;
                        C[cb + (size_t)mm * DM + cc] = stg[mm * 65 + cc];
                    }
                }
            }
            BAR1_128();
            if (tid == 0) MBAR_ARRIVE(sb + 96 + buf * 8);
        }
        BAR1_128();
        if (wid == 0) { TC_RELINQ(); TC_DEALLOC(tmem, 512); }
    }
#else
    (void)bias; (void)C;
#endif
}

// ============================================================
// Path A2 (fallback if tensormap unavailable): proven cp.async GEMM
// ============================================================
__global__ __launch_bounds__(128, 1)
void gemm_tf32_kernel(const float* __restrict__ A,
                      const float* __restrict__ W,
                      const float* __restrict__ bias,
                      float* __restrict__ C)
{
#if HAS_TC
    extern __shared__ __align__(1024) char smem[];
    const uint32_t sb = smem_u32(smem);
    const int tid = threadIdx.x;
    const int wid = tid >> 5;
    const int bm0 = blockIdx.y * TM;
    const int bn0 = blockIdx.x * TN;

    float* bsm = (float*)(smem + 128);
    bsm[tid] = bias[bn0 + tid];
    bsm[tid + 128] = bias[bn0 + 128 + tid];

    if (wid == 0) TC_ALLOC(sb + 0, 256);
    if (tid == 0) {
        for (int s = 0; s < NST; s++) MBAR_INIT(sb + 16 + s * 8, 1);
        MBAR_INIT(sb + 16 + NST * 8, 1);
    }
    __syncthreads();
    uint32_t tmem;
    asm volatile("ld.shared.b32 %0, [%1];" : "=r"(tmem) : "r"(sb + 0));

    const float* Abase = A + (size_t)bm0 * DM;
    const float* Wbase = W + (size_t)bn0 * DM;

#pragma unroll
    for (int j = 0; j < NST - 1; j++) {
        uint32_t abase = sb + SMEM_STAGE0 + j * STAGE_BYTES;
        uint32_t bbase = abase + A_STAGE_BYTES;
#pragma unroll
        for (int r = 0; r < 8; r++) {
            int i = tid + r * 128; int row = i >> 3, c16 = i & 7;
            CP_ASYNC16(abase + SWZ(row * 128 + c16 * 16),
                       Abase + (size_t)row * DM + j * BK + c16 * 4);
        }
#pragma unroll
        for (int r = 0; r < 16; r++) {
            int i = tid + r * 128; int row = i >> 3, c16 = i & 7;
            CP_ASYNC16(bbase + SWZ(row * 128 + c16 * 16),
                       Wbase + (size_t)row * DM + j * BK + c16 * 4);
        }
        CP_COMMIT();
    }

    for (int kc = 0; kc < NK; kc++) {
        const int j = kc + NST - 1;
        if (j < NK) {
            const int sl = j & (NST - 1);
            if (j >= NST) mbar_wait(sb + 16 + sl * 8, ((j >> 2) - 1) & 1);
            uint32_t abase = sb + SMEM_STAGE0 + sl * STAGE_BYTES;
            uint32_t bbase = abase + A_STAGE_BYTES;
#pragma unroll
            for (int r = 0; r < 8; r++) {
                int i = tid + r * 128; int row = i >> 3, c16 = i & 7;
                CP_ASYNC16(abase + SWZ(row * 128 + c16 * 16),
                           Abase + (size_t)row * DM + j * BK + c16 * 4);
            }
#pragma unroll
            for (int r = 0; r < 16; r++) {
                int i = tid + r * 128; int row = i >> 3, c16 = i & 7;
                CP_ASYNC16(bbase + SWZ(row * 128 + c16 * 16),
                           Wbase + (size_t)row * DM + j * BK + c16 * 4);
            }
        }
        CP_COMMIT();
        CP_WAIT3();
        __syncthreads();
        if (tid == 0) {
            FENCE_PROXY();
            const int sl = kc & (NST - 1);
            uint32_t abase = sb + SMEM_STAGE0 + sl * STAGE_BYTES;
            uint64_t ad = make_desc(abase);
            uint64_t bd = make_desc(abase + A_STAGE_BYTES);
#pragma unroll
            for (int t = 0; t < 4; t++)
                mma_tf32_ss(tmem, ad + t * 2, bd + t * 2, GEMM_IDESC, (uint32_t)((kc | t) != 0));
            TC_COMMIT(sb + 16 + sl * 8);
        }
    }
    if (tid == 0) TC_COMMIT(sb + 16 + NST * 8);
    mbar_wait(sb + 16 + NST * 8, 0);
    TC_FENCE_AFTER();

    float* stg = (float*)(smem + SMEM_STAGE0);
    const int m = tid;
#pragma unroll 1
    for (int ch = 0; ch < 4; ch++) {
        uint32_t r[64];
        TC_LD_X32(r, tmem + ch * 64);
        TC_LD_X32(r + 32, tmem + ch * 64 + 32);
        TC_WAIT_LD();
        __syncthreads();
#pragma unroll
        for (int c = 0; c < 64; c++)
            stg[m * 65 + c] = __uint_as_float(r[c]) + bsm[ch * 64 + c];
        __syncthreads();
        size_t cb = (size_t)bm0 * DM + bn0 + ch * 64;
#pragma unroll 8
        for (int it = 0; it < 64; it++) {
            int i = tid + it * 128;
            int mm = i >> 6, cc = i & 63;
            C[cb + (size_t)mm * DM + cc] = stg[mm * 65 + cc];
        }
    }
    __syncthreads();
    if (wid == 0) { TC_RELINQ(); TC_DEALLOC(tmem, 256); }
#else
    (void)A; (void)W; (void)bias; (void)C;
#endif
}

// ============================================================
// Path B: mma.sync tf32 fallback (empty when tcgen05 available)
// ============================================================
__global__ __launch_bounds__(256, 1)
void gemm_mma_kernel(const float* __restrict__ A,
                     const float* __restrict__ W,
                     const float* __restrict__ bias,
                     float* __restrict__ C)
{
#if defined(__CUDA_ARCH__) && !HAS_TC
    extern __shared__ __align__(16) float fsm[];
    float* As = fsm;
    float* Bs = fsm + 2 * 128 * 36;
    const uint32_t as_u = smem_u32(As);
    const uint32_t bs_u = smem_u32(Bs);

    const int tid = threadIdx.x;
    const int lane = tid & 31, warp = tid >> 5;
    const int wm = warp & 3;
    const int wn = warp >> 2;
    const int g = lane >> 2, ti = lane & 3;
    const int bm0 = blockIdx.y * 128;
    const int bn0 = blockIdx.x * 128;

    const float* Ag = A + (size_t)bm0 * DM;
    const float* Wg = W + (size_t)bn0 * DM;

    float c[2][8][4];
#pragma unroll
    for (int mi = 0; mi < 2; mi++)
#pragma unroll
        for (int ni = 0; ni < 8; ni++)
#pragma unroll
            for (int q = 0; q < 4; q++) c[mi][ni][q] = 0.f;

    auto load = [&](int st, int kc) {
        uint32_t ab = as_u + st * (128 * 36 * 4);
        uint32_t bb = bs_u + st * (128 * 36 * 4);
        const float* Ak = Ag + kc * 32;
        const float* Wk = Wg + kc * 32;
#pragma unroll
        for (int r = 0; r < 4; r++) {
            int i = tid + r * 256; int row = i >> 3, cc = i & 7;
            CP_ASYNC16(ab + row * 144 + cc * 16, Ak + (size_t)row * DM + cc * 4);
            CP_ASYNC16(bb + row * 144 + cc * 16, Wk + (size_t)row * DM + cc * 4);
        }
    };

    load(0, 0); CP_COMMIT();
    for (int kc = 0; kc < DM / 32; kc++) {
        if (kc + 1 < DM / 32) load((kc + 1) & 1, kc + 1);
        CP_COMMIT();
        CP_WAIT1();
        __syncthreads();
        const float* as_ = As + (kc & 1) * 128 * 36;
        const float* bs_ = Bs + (kc & 1) * 128 * 36;
#pragma unroll
        for (int ks = 0; ks < 4; ks++) {
            uint32_t a[2][4], b[8][2];
#pragma unroll
            for (int mi = 0; mi < 2; mi++) {
                int r0 = wm * 32 + mi * 16 + g;
                a[mi][0] = __float_as_uint(as_[r0 * 36 + ks * 8 + ti]);
                a[mi][1] = __float_as_uint(as_[(r0 + 8) * 36 + ks * 8 + ti]);
                a[mi][2] = __float_as_uint(as_[r0 * 36 + ks * 8 + ti + 4]);
                a[mi][3] = __float_as_uint(as_[(r0 + 8) * 36 + ks * 8 + ti + 4]);
            }
#pragma unroll
            for (int ni = 0; ni < 8; ni++) {
                int n0 = wn * 64 + ni * 8 + g;
                b[ni][0] = __float_as_uint(bs_[n0 * 36 + ks * 8 + ti]);
                b[ni][1] = __float_as_uint(bs_[n0 * 36 + ks * 8 + ti + 4]);
            }
#pragma unroll
            for (int mi = 0; mi < 2; mi++)
#pragma unroll
                for (int ni = 0; ni < 8; ni++)
                    MMA_TF32(c[mi][ni], a[mi], b[ni]);
        }
        __syncthreads();
    }

#pragma unroll
    for (int mi = 0; mi < 2; mi++) {
        int r0 = bm0 + wm * 32 + mi * 16 + g;
#pragma unroll
        for (int ni = 0; ni < 8; ni++) {
            int c0 = bn0 + wn * 64 + ni * 8 + ti * 2;
            float b0 = bias[c0], b1 = bias[c0 + 1];
            C[(size_t)r0 * DM + c0]           = c[mi][ni][0] + b0;
            C[(size_t)r0 * DM + c0 + 1]       = c[mi][ni][1] + b1;
            C[(size_t)(r0 + 8) * DM + c0]     = c[mi][ni][2] + b0;
            C[(size_t)(r0 + 8) * DM + c0 + 1] = c[mi][ni][3] + b1;
        }
    }
#else
    (void)A; (void)W; (void)bias; (void)C;
#endif
}

// ============================================================
// All-4-weights tf32 rounding in one launch. WN4 = 2^18 float4 per weight.
// ============================================================
__global__ void round4_kernel(const float4* __restrict__ q, const float4* __restrict__ k,
                              const float4* __restrict__ v, const float4* __restrict__ o,
                              float4* __restrict__ dst)
{
    int i = blockIdx.x * blockDim.x + threadIdx.x;   // 0 .. 4*2^18-1
    int region = i >> 18;
    const float4* src = (region == 0) ? q : (region == 1) ? k : (region == 2) ? v : o;
    float4 val = src[i & 0x3FFFF];
    val.x = rtf(val.x); val.y = rtf(val.y); val.z = rtf(val.z); val.w = rtf(val.w);
    dst[i] = val;
}

// ============================================================
// Fused KV accumulation with inline depthwise conv + fmap.
// ============================================================
__global__ __launch_bounds__(256)
void kv_accum_kernel(const float* __restrict__ pk, const float* __restrict__ pv,
                     const float* __restrict__ kcw, const float* __restrict__ kcb,
                     const float* __restrict__ vcw, const float* __restrict__ vcb)
{
    const int bh = blockIdx.x;
    const int b = bh / HH, h = bh % HH;
    const int split = blockIdx.y;

    __shared__ float Pk[34 * 64], Pv[34 * 64];
    __shared__ float Ks[32][64], Vs[32][64];
    __shared__ float Wk[192], Bk[64], Wv[192], Bv[64];

    const int t = threadIdx.x;
    if (t < 192) { Wk[t] = kcw[t]; Wv[t] = vcw[t]; }
    if (t < 64)  { Bk[t] = kcb[t]; Bv[t] = vcb[t]; }

    const int d = t >> 2;
    const int e0 = t & 3;

    float acc[16];
#pragma unroll
    for (int j = 0; j < 16; j++) acc[j] = 0.f;
    float ksum = 0.f;

    const size_t base = (size_t)b * SS * DM + h * HD;
    const int sbeg = split * (SS / NSPLIT);

    for (int s0 = sbeg; s0 < sbeg + SS / NSPLIT; s0 += 32) {
#pragma unroll
        for (int r = 0; r < 9; r++) {
            int li = r * 256 + t;
            if (li < 34 * 64) {
                int lr = li >> 6, ld = li & 63;
                int s = s0 - 2 + lr;
                float kv_ = 0.f, vv_ = 0.f;
                if (s >= 0) {
                    size_t g = base + (size_t)s * DM + ld;
                    kv_ = pk[g]; vv_ = pv[g];
                }
                Pk[li] = kv_; Pv[li] = vv_;
            }
        }
        __syncthreads();
#pragma unroll
        for (int r = 0; r < 8; r++) {
            int li = r * 256 + t;
            int lr = li >> 6, ld = li & 63;
            float kk = Bk[ld] + Wk[ld*3+2]*Pk[(lr+2)*64+ld]
                              + Wk[ld*3+1]*Pk[(lr+1)*64+ld]
                              + Wk[ld*3+0]*Pk[lr*64+ld];
            Ks[lr][ld] = (kk > 0.f) ? (kk + 1.f) : expf(kk);
            float vv = Bv[ld] + Wv[ld*3+2]*Pv[(lr+2)*64+ld]
                              + Wv[ld*3+1]*Pv[(lr+1)*64+ld]
                              + Wv[ld*3+0]*Pv[lr*64+ld];
            Vs[lr][ld] = vv;
        }
        __syncthreads();
#pragma unroll 4
        for (int s = 0; s < 32; s++) {
            float kd = Ks[s][d];
            ksum += kd;
#pragma unroll
            for (int j = 0; j < 16; j++)
                acc[j] += kd * Vs[s][e0 + 4 * j];
        }
        __syncthreads();
    }

    float* kvout = g_KVpart + (((size_t)split * NBH + bh) * HD + d) * HD;
#pragma unroll
    for (int j = 0; j < 16; j++) kvout[e0 + 4 * j] = acc[j];
    if (e0 == 0) g_Ksump[((size_t)split * NBH + bh) * HD + d] = ksum;
}

__global__ void kv_reduce_kernel()
{
    int i = blockIdx.x * blockDim.x + threadIdx.x;
    float s = 0.f;
#pragma unroll
    for (int p = 0; p < NSPLIT; p++) s += g_KVpart[(size_t)p * NBH * HD * HD + i];
    g_KV[i] = s;
    if (i < NBH * HD) {
        float s2 = 0.f;
#pragma unroll
        for (int p = 0; p < NSPLIT; p++) s2 += g_Ksump[p * NBH * HD + i];
        g_Ksum[i] = s2;
    }
}

// ============================================================
// V_new with inline conv+fmap; tf32-rounded output.
// ============================================================
__global__ __launch_bounds__(256)
void vnew_kernel(const float* __restrict__ pq, float* __restrict__ out,
                 const float* __restrict__ qcw, const float* __restrict__ qcb)
{
    const int bh = blockIdx.x;
    const int b = bh / HH, h = bh % HH;
    const int s0 = blockIdx.y * 32;

    __shared__ float KVs[64 * 64];
    __shared__ float Kss[64];
    __shared__ float Pq[34 * 64];
    __shared__ float Qs[32][64];
    __shared__ float Wq[192], Bq[64];

    const int t = threadIdx.x;
    if (t < 192) Wq[t] = qcw[t];
    if (t < 64)  Bq[t] = qcb[t];

    const float* kvsrc = g_KV + (size_t)bh * HD * HD;
#pragma unroll
    for (int r = 0; r < 16; r++) KVs[r * 256 + t] = kvsrc[r * 256 + t];
    if (t < 64) Kss[t] = g_Ksum[bh * HD + t] + EPS;

    const size_t base = (size_t)b * SS * DM + h * HD;
#pragma unroll
    for (int r = 0; r < 9; r++) {
        int li = r * 256 + t;
        if (li < 34 * 64) {
            int lr = li >> 6, ld = li & 63;
            int s = s0 - 2 + lr;
            Pq[li] = (s >= 0) ? pq[base + (size_t)s * DM + ld] : 0.f;
        }
    }
    __syncthreads();
#pragma unroll
    for (int r = 0; r < 8; r++) {
        int li = r * 256 + t;
        int lr = li >> 6, ld = li & 63;
        float q = Bq[ld] + Wq[ld*3+2]*Pq[(lr+2)*64+ld]
                         + Wq[ld*3+1]*Pq[(lr+1)*64+ld]
                         + Wq[ld*3+0]*Pq[lr*64+ld];
        Qs[lr][ld] = (q > 0.f) ? (q + 1.f) : expf(q);
    }
    __syncthreads();

    const int sl = t >> 3;
    const int e0 = (t & 7) * 8;

    float denom = 0.f;
#pragma unroll
    for (int dd = 0; dd < 64; dd++) denom += Qs[sl][dd] * Kss[dd];
    float zinv = 1.f / denom;

    float acc[8];
#pragma unroll
    for (int j = 0; j < 8; j++) acc[j] = 0.f;
#pragma unroll
    for (int dd = 0; dd < 64; dd++) {
        float qd = Qs[sl][dd];
#pragma unroll
        for (int j = 0; j < 8; j++) acc[j] += KVs[dd * 64 + e0 + j] * qd;
    }

    size_t ob = base + (size_t)(s0 + sl) * DM + e0;
#pragma unroll
    for (int j = 0; j < 8; j++) out[ob + j] = rtf(acc[j] * zinv);
}

// ============================================================
// Host: tensormap creation via driver entry point
// ============================================================
typedef CUresult (*EncodeTiledFn)(CUtensorMap*, CUtensorMapDataType, cuuint32_t, void*,
                                  const cuuint64_t*, const cuuint64_t*,
                                  const cuuint32_t*, const cuuint32_t*,
                                  CUtensorMapInterleave, CUtensorMapSwizzle,
                                  CUtensorMapL2promotion, CUtensorMapFloatOOBfill);

static bool make_map2d(EncodeTiledFn enc, CUtensorMap* m, const float* ptr,
                       uint64_t rows, uint32_t boxRows)
{
    cuuint64_t dims[2]    = {DM, rows};
    cuuint64_t strides[1] = {DM * sizeof(float)};
    cuuint32_t box[2]     = {BK, boxRows};
    cuuint32_t es[2]      = {1, 1};
    return enc(m, CU_TENSOR_MAP_DATA_TYPE_FLOAT32, 2, (void*)ptr,
               dims, strides, box, es,
               CU_TENSOR_MAP_INTERLEAVE_NONE, CU_TENSOR_MAP_SWIZZLE_128B,
               CU_TENSOR_MAP_L2_PROMOTION_L2_128B,
               CU_TENSOR_MAP_FLOAT_OOB_FILL_NONE) == CUDA_SUCCESS;
}

extern "C" void kernel_launch(void* const* d_in, const int* in_sizes, int n_in,
                              void* d_out, int out_size)
{
    const float* query = (const float*)d_in[0];
    const float* key   = (const float*)d_in[1];
    const float* value = (const float*)d_in[2];
    const float* q_w   = (const float*)d_in[3];
    const float* q_b   = (const float*)d_in[4];
    const float* k_w   = (const float*)d_in[5];
    const float* k_b   = (const float*)d_in[6];
    const float* v_w   = (const float*)d_in[7];
    const float* v_b   = (const float*)d_in[8];
    const float* o_w   = (const float*)d_in[9];
    const float* o_b   = (const float*)d_in[10];
    const float* qc_w  = (const float*)d_in[11];
    const float* qc_b  = (const float*)d_in[12];
    const float* kc_w  = (const float*)d_in[13];
    const float* kc_b  = (const float*)d_in[14];
    const float* vc_w  = (const float*)d_in[15];
    const float* vc_b  = (const float*)d_in[16];
    float* out = (float*)d_out;

    float *proj, *vnew, *rw;
    cudaGetSymbolAddress((void**)&proj, g_proj);
    cudaGetSymbolAddress((void**)&vnew, g_vnew);
    cudaGetSymbolAddress((void**)&rw,   g_rw);
    float* pq = proj;  float* pk = proj + (size_t)NEL;  float* pv = proj + 2 * (size_t)NEL;
    float* rqw = rw;                       float* rkw = rw + (size_t)DM * DM;
    float* rvw = rw + 2 * (size_t)DM * DM; float* row_ = rw + 3 * (size_t)DM * DM;

    cudaFuncSetAttribute(gemm_persist_kernel,
                         cudaFuncAttributeMaxDynamicSharedMemorySize, PSMEM);
    cudaFuncSetAttribute(gemm_tf32_kernel,
                         cudaFuncAttributeMaxDynamicSharedMemorySize, GEMM_SMEM);
    cudaFuncSetAttribute(gemm_mma_kernel,
                         cudaFuncAttributeMaxDynamicSharedMemorySize, MMA_SMEM);

    EncodeTiledFn enc = nullptr;
    {
        void* p = nullptr;
        cudaDriverEntryPointQueryResult qr;
        if (cudaGetDriverEntryPoint("cuTensorMapEncodeTiled", &p,
                                    cudaEnableDefault, &qr) == cudaSuccess && p)
            enc = (EncodeTiledFn)p;
    }

    CUtensorMap mAq{}, mAk{}, mAv{}, mAo{}, mWq{}, mWk{}, mWv{}, mWo{};
    bool use_tma = (enc != nullptr);
    if (use_tma) {
        use_tma = make_map2d(enc, &mAq, query, MTOT, TM)
               && make_map2d(enc, &mAk, key,   MTOT, TM)
               && make_map2d(enc, &mAv, value, MTOT, TM)
               && make_map2d(enc, &mAo, vnew,  MTOT, TM)
               && make_map2d(enc, &mWq, rqw,  DM, TN)
               && make_map2d(enc, &mWk, rkw,  DM, TN)
               && make_map2d(enc, &mWv, rvw,  DM, TN)
               && make_map2d(enc, &mWo, row_, DM, TN);
    }

    // 0) round all weights to tf32 (RN), one launch
    round4_kernel<<<4 * (DM * DM / 4) / 256, 256>>>(
        (const float4*)q_w, (const float4*)k_w, (const float4*)v_w, (const float4*)o_w,
        (float4*)rw);

    dim3 ggrid_tc(DM / TN, MTOT / TM);    // (4, 128) fallback grid
    dim3 ggrid_mma(DM / 128, MTOT / 128);

#define LAUNCH_GEMM(MA, MW, Araw, Wr, Bias, Cout) do { \
        gemm_mma_kernel<<<ggrid_mma, 256, MMA_SMEM>>>(Araw, Wr, Bias, Cout); \
        if (use_tma) \
            gemm_persist_kernel<<<GRID_P, 160, PSMEM>>>(MA, MW, Bias, Cout); \
        else \
            gemm_tf32_kernel<<<ggrid_tc, 128, GEMM_SMEM>>>(Araw, Wr, Bias, Cout); \
    } while (0)

    // 1) QKV projections
    LAUNCH_GEMM(mAq, mWq, query, rqw, q_b, pq);
    LAUNCH_GEMM(mAk, mWk, key,   rkw, k_b, pk);
    LAUNCH_GEMM(mAv, mWv, value, rvw, v_b, pv);

    // 2) KV + Ksum (conv fused)
    kv_accum_kernel<<<dim3(NBH, NSPLIT), 256>>>(pk, pv, kc_w, kc_b, vc_w, vc_b);
    kv_reduce_kernel<<<(NBH * HD * HD) / 256, 256>>>();

    // 3) V_new (conv_q fused)
    vnew_kernel<<<dim3(NBH, SS / 32), 256>>>(pq, vnew, qc_w, qc_b);

    // 4) output projection
    LAUNCH_GEMM(mAo, mWo, vnew, row_, o_b, out);
#undef LAUNCH_GEMM
}

// round 12
// speedup vs baseline: 1.8493x; 1.0082x over previous
#include <cuda_runtime.h>
#include <cuda.h>
#include <math.h>
#include <stdint.h>

// Problem constants
#define BB 4
#define SS 4096
#define DM 1024
#define HH 16
#define HD 64
#define MTOT (BB*SS)            // 16384
#define NEL (MTOT*DM)           // 16,777,216
#define EPS 1e-6f
#define NBH (BB*HH)             // 64
#define NSPLIT 8

// ---- arch-feature detection ----
#if defined(__CUDA_ARCH_FEAT_SM103_ALL) || defined(__CUDA_ARCH_FEAT_SM100_ALL) || \
    (defined(__CUDA_ARCH_SPECIFIC__) && (__CUDA_ARCH_SPECIFIC__ == 1030 || __CUDA_ARCH_SPECIFIC__ == 1000)) || \
    (defined(__CUDA_ARCH_FAMILY_SPECIFIC__) && (__CUDA_ARCH_FAMILY_SPECIFIC__ == 1030 || __CUDA_ARCH_FAMILY_SPECIFIC__ == 1000))
#define HAS_TC 1
#else
#define HAS_TC 0
#endif

// tcgen05 GEMM tiling
#define TM 128
#define TN 256
#define BK 32                   // floats per k-chunk = 128 B (one SW128 row)
#define NK (DM/BK)              // 32
#define NST 4
#define A_STAGE_BYTES (TM*128)  // 16 KB
#define B_STAGE_BYTES (TN*128)  // 32 KB
#define STAGE_BYTES (A_STAGE_BYTES + B_STAGE_BYTES)   // 48 KB
#define SMEM_STAGE0 2048
#define GEMM_SMEM (SMEM_STAGE0 + NST*STAGE_BYTES)     // 198656 (fallback)

// persistent kernel
#define NTILES 4
#define GRID_P 128
#define NKTOT (NTILES*NK)       // 128 chunks
#define EPI_STG_OFF (SMEM_STAGE0 + NST*STAGE_BYTES)   // 198656
#define EPI_STG_BYTES (64*65*4)                       // 16640
#define PSMEM (EPI_STG_OFF + EPI_STG_BYTES)           // 215296

// -------- scratch --------
__device__ float g_proj[3 * NEL];
__device__ float g_vnew[NEL];
__device__ float g_rw[4 * DM * DM];
__device__ float g_KVpart[NSPLIT * NBH * HD * HD];
__device__ float g_Ksump[NSPLIT * NBH * HD];
__device__ float g_KV[NBH * HD * HD];
__device__ float g_Ksum[NBH * HD];
__device__ float g_dummy[32];

// ============================================================
// PTX helpers
// ============================================================
__device__ __forceinline__ uint32_t smem_u32(const void* p) {
    uint32_t a;
    asm("{ .reg .u64 t; cvta.to.shared.u64 t, %1; cvt.u32.u64 %0, t; }" : "=r"(a) : "l"(p));
    return a;
}
#define SWZ(o) ((o) ^ (((o) >> 3) & 0x70))

#define CP_ASYNC16(dst, src) \
    asm volatile("cp.async.cg.shared.global [%0], [%1], 16;" :: "r"(dst), "l"(src) : "memory")
#define CP_COMMIT() asm volatile("cp.async.commit_group;" ::: "memory")
#define CP_WAIT3()  asm volatile("cp.async.wait_group 3;" ::: "memory")

#define MBAR_INIT(addr, cnt) \
    asm volatile("mbarrier.init.shared.b64 [%0], %1;" :: "r"(addr), "r"(cnt) : "memory")
#define MBAR_EXPECT_TX(addr, bytes) \
    asm volatile("mbarrier.arrive.expect_tx.shared.b64 _, [%0], %1;" :: "r"(addr), "r"(bytes) : "memory")
#define MBAR_ARRIVE(addr) \
    asm volatile("mbarrier.arrive.shared.b64 _, [%0];" :: "r"(addr) : "memory")
__device__ __forceinline__ void mbar_wait(uint32_t addr, uint32_t phase) {
    asm volatile(
        "{\n\t.reg .pred P;\n\t"
        "W_%=:\n\t"
        "mbarrier.try_wait.parity.shared.b64 P, [%0], %1, 0x989680;\n\t"
        "@P bra D_%=;\n\t"
        "bra W_%=;\n\t"
        "D_%=:\n\t}"
        :: "r"(addr), "r"(phase) : "memory");
}
#define BAR1_128() asm volatile("bar.sync 1, 128;" ::: "memory")

__device__ __forceinline__ float rtf(float x) {
    asm("cvt.rna.tf32.f32 %0, %0;" : "+f"(x));
    return x;
}

#if HAS_TC
#define TC_ALLOC(sm, n)   asm volatile("tcgen05.alloc.cta_group::1.sync.aligned.shared::cta.b32 [%0], %1;" :: "r"(sm), "r"(n) : "memory")
#define TC_DEALLOC(t, n)  asm volatile("tcgen05.dealloc.cta_group::1.sync.aligned.b32 %0, %1;" :: "r"(t), "r"(n))
#define TC_RELINQ()       asm volatile("tcgen05.relinquish_alloc_permit.cta_group::1.sync.aligned;")
#define TC_COMMIT(mb)     asm volatile("tcgen05.commit.cta_group::1.mbarrier::arrive::one.shared::cluster.b64 [%0];" :: "r"(mb) : "memory")
#define TC_FENCE_AFTER()  asm volatile("tcgen05.fence::after_thread_sync;" ::: "memory")
#define TC_WAIT_LD()      asm volatile("tcgen05.wait::ld.sync.aligned;" ::: "memory")
#define FENCE_PROXY()     asm volatile("fence.proxy.async.shared::cta;" ::: "memory")

#define TMA_LD_2D(smem, map, x, y, mb) \
    asm volatile("cp.async.bulk.tensor.2d.shared::cta.global.tile.mbarrier::complete_tx::bytes " \
        "[%0], [%1, {%2, %3}], [%4];" \
        :: "r"(smem), "l"(map), "r"(x), "r"(y), "r"(mb) : "memory")

#define TC_LD_X32(r, ta) \
    asm volatile( \
        "tcgen05.ld.sync.aligned.32x32b.x32.b32 " \
        "{%0, %1, %2, %3, %4, %5, %6, %7, " \
        " %8, %9, %10, %11, %12, %13, %14, %15, " \
        " %16, %17, %18, %19, %20, %21, %22, %23, " \
        " %24, %25, %26, %27, %28, %29, %30, %31}, [%32];" \
        : "=r"((r)[0]),  "=r"((r)[1]),  "=r"((r)[2]),  "=r"((r)[3]), \
          "=r"((r)[4]),  "=r"((r)[5]),  "=r"((r)[6]),  "=r"((r)[7]), \
          "=r"((r)[8]),  "=r"((r)[9]),  "=r"((r)[10]), "=r"((r)[11]), \
          "=r"((r)[12]), "=r"((r)[13]), "=r"((r)[14]), "=r"((r)[15]), \
          "=r"((r)[16]), "=r"((r)[17]), "=r"((r)[18]), "=r"((r)[19]), \
          "=r"((r)[20]), "=r"((r)[21]), "=r"((r)[22]), "=r"((r)[23]), \
          "=r"((r)[24]), "=r"((r)[25]), "=r"((r)[26]), "=r"((r)[27]), \
          "=r"((r)[28]), "=r"((r)[29]), "=r"((r)[30]), "=r"((r)[31]) \
        : "r"(ta))

__device__ __forceinline__ uint64_t make_desc(uint32_t addr) {
    const uint64_t base =
        (uint64_t(2)  << 61) | (uint64_t(1) << 46) | (uint64_t(64) << 32) | (uint64_t(1) << 16);
    return base | ((uint64_t)(addr >> 4) & 0x3FFF);
}

__device__ __forceinline__ void mma_tf32_ss(uint32_t d_tmem, uint64_t a_desc, uint64_t b_desc,
                                            uint32_t idesc, uint32_t enable) {
    asm volatile(
        "{\n\t"
        ".reg .pred p;\n\t"
        "setp.ne.u32 p, %4, 0;\n\t"
        "tcgen05.mma.cta_group::1.kind::tf32 [%0], %1, %2, %3, {%5, %5, %5, %5}, p;\n\t"
        "}"
        :: "r"(d_tmem), "l"(a_desc), "l"(b_desc), "r"(idesc), "r"(enable), "r"(0u)
        : "memory");
}

#define GEMM_IDESC ((1u << 4) | (2u << 7) | (2u << 10) | ((TN / 8) << 17) | ((TM / 16) << 24))
#endif  // HAS_TC

// ============================================================
// Persistent warp-specialized TMA GEMM. 128 CTAs x 4 M-tiles.
// 192 threads: warps 0-3 epilogue; warp4 lane0 = TMA producer;
// warp5 lane0 = MMA consumer.
// Barriers: full[s]@16+8s, empty[s]@48+8s, mmadone[b]@80+8b, epifree[b]@96+8b
// ============================================================
__global__ __launch_bounds__(192, 1)
void gemm_persist_kernel(const __grid_constant__ CUtensorMap mapA,
                         const __grid_constant__ CUtensorMap mapW,
                         const float* __restrict__ bias,
                         float* __restrict__ C)
{
#if HAS_TC
    extern __shared__ __align__(1024) char smem[];
    const uint32_t sb = smem_u32(smem);
    const int tid = threadIdx.x;
    const int wid = tid >> 5;
    const int bn0 = (blockIdx.x & 3) * TN;
    const int bmBase = (blockIdx.x >> 2) * NTILES;

    float* bsm = (float*)(smem + 128);
    if (tid < 128) { bsm[tid] = bias[bn0 + tid]; bsm[tid + 128] = bias[bn0 + 128 + tid]; }

    if (wid == 0) TC_ALLOC(sb, 512);
    if (tid == 0) {
        for (int s = 0; s < NST; s++) { MBAR_INIT(sb + 16 + s * 8, 1); MBAR_INIT(sb + 48 + s * 8, 1); }
        MBAR_INIT(sb + 80, 1); MBAR_INIT(sb + 88, 1);
        MBAR_INIT(sb + 96, 1); MBAR_INIT(sb + 104, 1);
    }
    __syncthreads();
    uint32_t tmem;
    asm volatile("ld.shared.b32 %0, [%1];" : "=r"(tmem) : "r"(sb));

    if (tid == 128) {
        // ---- TMA producer ----
        for (int j = 0; j < NKTOT; j++) {
            const int sl = j & 3;
            if (j >= NST) mbar_wait(sb + 48 + sl * 8, ((j >> 2) - 1) & 1);
            uint32_t ab = sb + SMEM_STAGE0 + sl * STAGE_BYTES;
            MBAR_EXPECT_TX(sb + 16 + sl * 8, STAGE_BYTES);
            TMA_LD_2D(ab, &mapA, (j & 31) * BK, (bmBase + (j >> 5)) * TM, sb + 16 + sl * 8);
            TMA_LD_2D(ab + A_STAGE_BYTES, &mapW, (j & 31) * BK, bn0, sb + 16 + sl * 8);
        }
    } else if (tid == 160) {
        // ---- MMA consumer ----
        for (int c = 0; c < NKTOT; c++) {
            const int sl = c & 3, kc = c & 31, tc = c >> 5, buf = tc & 1;
            mbar_wait(sb + 16 + sl * 8, (c >> 2) & 1);
            if (kc == 0 && tc >= 2) mbar_wait(sb + 96 + buf * 8, 0);  // tile tc-2 epilogue done
            uint32_t ab = sb + SMEM_STAGE0 + sl * STAGE_BYTES;
            uint64_t ad = make_desc(ab);
            uint64_t bd = make_desc(ab + A_STAGE_BYTES);
            uint32_t dt = tmem + buf * 256;
#pragma unroll
            for (int t4 = 0; t4 < 4; t4++)
                mma_tf32_ss(dt, ad + t4 * 2, bd + t4 * 2, GEMM_IDESC, (uint32_t)((kc | t4) != 0));
            TC_COMMIT(sb + 48 + sl * 8);
            if (kc == NK - 1) TC_COMMIT(sb + 80 + buf * 8);
        }
    } else if (tid < 128) {
        // ---- epilogue workers ----
        float* stg = (float*)(smem + EPI_STG_OFF);
#pragma unroll 1
        for (int t = 0; t < NTILES; t++) {
            const int buf = t & 1;
            mbar_wait(sb + 80 + buf * 8, (t >> 1) & 1);
            TC_FENCE_AFTER();
            const int bm0 = (bmBase + t) * TM;
            const uint32_t dt = tmem + buf * 256;
#pragma unroll 1
            for (int ch = 0; ch < 4; ch++) {
                uint32_t r[64];
                TC_LD_X32(r, dt + ch * 64);
                TC_LD_X32(r + 32, dt + ch * 64 + 32);
                TC_WAIT_LD();
#pragma unroll 1
                for (int p = 0; p < 2; p++) {
                    BAR1_128();
                    if ((tid >> 6) == p) {
                        int m = tid & 63;
#pragma unroll
                        for (int cc = 0; cc < 64; cc++)
                            stg[m * 65 + cc] = __uint_as_float(r[cc]) + bsm[ch * 64 + cc];
                    }
                    BAR1_128();
                    size_t cb = (size_t)(bm0 + p * 64) * DM + bn0 + ch * 64;
#pragma unroll 8
                    for (int it = 0; it < 32; it++) {
                        int i = tid + it * 128;
                        int mm = i >> 6, cc = i & 63;
                        C[cb + (size_t)mm * DM + cc] = stg[mm * 65 + cc];
                    }
                }
            }
            BAR1_128();
            if (tid == 0) MBAR_ARRIVE(sb + 96 + buf * 8);
        }
        BAR1_128();
        if (wid == 0) { TC_RELINQ(); TC_DEALLOC(tmem, 512); }
    }
#else
    (void)bias; (void)C;
#endif
}

// ============================================================
// Fallback (tensormap unavailable): proven cp.async tcgen05 GEMM
// ============================================================
__global__ __launch_bounds__(128, 1)
void gemm_tf32_kernel(const float* __restrict__ A,
                      const float* __restrict__ W,
                      const float* __restrict__ bias,
                      float* __restrict__ C)
{
#if HAS_TC
    extern __shared__ __align__(1024) char smem[];
    const uint32_t sb = smem_u32(smem);
    const int tid = threadIdx.x;
    const int wid = tid >> 5;
    const int bm0 = blockIdx.y * TM;
    const int bn0 = blockIdx.x * TN;

    float* bsm = (float*)(smem + 128);
    bsm[tid] = bias[bn0 + tid];
    bsm[tid + 128] = bias[bn0 + 128 + tid];

    if (wid == 0) TC_ALLOC(sb + 0, 256);
    if (tid == 0) {
        for (int s = 0; s < NST; s++) MBAR_INIT(sb + 16 + s * 8, 1);
        MBAR_INIT(sb + 16 + NST * 8, 1);
    }
    __syncthreads();
    uint32_t tmem;
    asm volatile("ld.shared.b32 %0, [%1];" : "=r"(tmem) : "r"(sb + 0));

    const float* Abase = A + (size_t)bm0 * DM;
    const float* Wbase = W + (size_t)bn0 * DM;

#pragma unroll
    for (int j = 0; j < NST - 1; j++) {
        uint32_t abase = sb + SMEM_STAGE0 + j * STAGE_BYTES;
        uint32_t bbase = abase + A_STAGE_BYTES;
#pragma unroll
        for (int r = 0; r < 8; r++) {
            int i = tid + r * 128; int row = i >> 3, c16 = i & 7;
            CP_ASYNC16(abase + SWZ(row * 128 + c16 * 16),
                       Abase + (size_t)row * DM + j * BK + c16 * 4);
        }
#pragma unroll
        for (int r = 0; r < 16; r++) {
            int i = tid + r * 128; int row = i >> 3, c16 = i & 7;
            CP_ASYNC16(bbase + SWZ(row * 128 + c16 * 16),
                       Wbase + (size_t)row * DM + j * BK + c16 * 4);
        }
        CP_COMMIT();
    }

    for (int kc = 0; kc < NK; kc++) {
        const int j = kc + NST - 1;
        if (j < NK) {
            const int sl = j & (NST - 1);
            if (j >= NST) mbar_wait(sb + 16 + sl * 8, ((j >> 2) - 1) & 1);
            uint32_t abase = sb + SMEM_STAGE0 + sl * STAGE_BYTES;
            uint32_t bbase = abase + A_STAGE_BYTES;
#pragma unroll
            for (int r = 0; r < 8; r++) {
                int i = tid + r * 128; int row = i >> 3, c16 = i & 7;
                CP_ASYNC16(abase + SWZ(row * 128 + c16 * 16),
                           Abase + (size_t)row * DM + j * BK + c16 * 4);
            }
#pragma unroll
            for (int r = 0; r < 16; r++) {
                int i = tid + r * 128; int row = i >> 3, c16 = i & 7;
                CP_ASYNC16(bbase + SWZ(row * 128 + c16 * 16),
                           Wbase + (size_t)row * DM + j * BK + c16 * 4);
            }
        }
        CP_COMMIT();
        CP_WAIT3();
        __syncthreads();
        if (tid == 0) {
            FENCE_PROXY();
            const int sl = kc & (NST - 1);
            uint32_t abase = sb + SMEM_STAGE0 + sl * STAGE_BYTES;
            uint64_t ad = make_desc(abase);
            uint64_t bd = make_desc(abase + A_STAGE_BYTES);
#pragma unroll
            for (int t = 0; t < 4; t++)
                mma_tf32_ss(tmem, ad + t * 2, bd + t * 2, GEMM_IDESC, (uint32_t)((kc | t) != 0));
            TC_COMMIT(sb + 16 + sl * 8);
        }
    }
    if (tid == 0) TC_COMMIT(sb + 16 + NST * 8);
    mbar_wait(sb + 16 + NST * 8, 0);
    TC_FENCE_AFTER();

    float* stg = (float*)(smem + SMEM_STAGE0);
    const int m = tid;
#pragma unroll 1
    for (int ch = 0; ch < 4; ch++) {
        uint32_t r[64];
        TC_LD_X32(r, tmem + ch * 64);
        TC_LD_X32(r + 32, tmem + ch * 64 + 32);
        TC_WAIT_LD();
        __syncthreads();
#pragma unroll
        for (int c = 0; c < 64; c++)
            stg[m * 65 + c] = __uint_as_float(r[c]) + bsm[ch * 64 + c];
        __syncthreads();
        size_t cb = (size_t)bm0 * DM + bn0 + ch * 64;
#pragma unroll 8
        for (int it = 0; it < 64; it++) {
            int i = tid + it * 128;
            int mm = i >> 6, cc = i & 63;
            C[cb + (size_t)mm * DM + cc] = stg[mm * 65 + cc];
        }
    }
    __syncthreads();
    if (wid == 0) { TC_RELINQ(); TC_DEALLOC(tmem, 256); }
#else
    (void)A; (void)W; (void)bias; (void)C;
#endif
}

// ============================================================
// Tiny dummy kernel — aligns ncu's profiled launch index (-s 5)
// onto the first gemm_persist launch. Removed once diagnosed.
// ============================================================
__global__ void dummy_kernel(int tag)
{
    if (threadIdx.x == 0) g_dummy[tag & 31] = (float)tag;
}

// ============================================================
// All-4-weights tf32 rounding in one launch
// ============================================================
__global__ void round4_kernel(const float4* __restrict__ q, const float4* __restrict__ k,
                              const float4* __restrict__ v, const float4* __restrict__ o,
                              float4* __restrict__ dst)
{
    int i = blockIdx.x * blockDim.x + threadIdx.x;
    int region = i >> 18;
    const float4* src = (region == 0) ? q : (region == 1) ? k : (region == 2) ? v : o;
    float4 val = src[i & 0x3FFFF];
    val.x = rtf(val.x); val.y = rtf(val.y); val.z = rtf(val.z); val.w = rtf(val.w);
    dst[i] = val;
}

// ============================================================
// Fused KV accumulation with inline depthwise conv + fmap.
// ============================================================
__global__ __launch_bounds__(256)
void kv_accum_kernel(const float* __restrict__ pk, const float* __restrict__ pv,
                     const float* __restrict__ kcw, const float* __restrict__ kcb,
                     const float* __restrict__ vcw, const float* __restrict__ vcb)
{
    const int bh = blockIdx.x;
    const int b = bh / HH, h = bh % HH;
    const int split = blockIdx.y;

    __shared__ float Pk[34 * 64], Pv[34 * 64];
    __shared__ float Ks[32][64], Vs[32][64];
    __shared__ float Wk[192], Bk[64], Wv[192], Bv[64];

    const int t = threadIdx.x;
    if (t < 192) { Wk[t] = kcw[t]; Wv[t] = vcw[t]; }
    if (t < 64)  { Bk[t] = kcb[t]; Bv[t] = vcb[t]; }

    const int d = t >> 2;
    const int e0 = t & 3;

    float acc[16];
#pragma unroll
    for (int j = 0; j < 16; j++) acc[j] = 0.f;
    float ksum = 0.f;

    const size_t base = (size_t)b * SS * DM + h * HD;
    const int sbeg = split * (SS / NSPLIT);

    for (int s0 = sbeg; s0 < sbeg + SS / NSPLIT; s0 += 32) {
#pragma unroll
        for (int r = 0; r < 9; r++) {
            int li = r * 256 + t;
            if (li < 34 * 64) {
                int lr = li >> 6, ld = li & 63;
                int s = s0 - 2 + lr;
                float kv_ = 0.f, vv_ = 0.f;
                if (s >= 0) {
                    size_t g = base + (size_t)s * DM + ld;
                    kv_ = pk[g]; vv_ = pv[g];
                }
                Pk[li] = kv_; Pv[li] = vv_;
            }
        }
        __syncthreads();
#pragma unroll
        for (int r = 0; r < 8; r++) {
            int li = r * 256 + t;
            int lr = li >> 6, ld = li & 63;
            float kk = Bk[ld] + Wk[ld*3+2]*Pk[(lr+2)*64+ld]
                              + Wk[ld*3+1]*Pk[(lr+1)*64+ld]
                              + Wk[ld*3+0]*Pk[lr*64+ld];
            Ks[lr][ld] = (kk > 0.f) ? (kk + 1.f) : expf(kk);
            float vv = Bv[ld] + Wv[ld*3+2]*Pv[(lr+2)*64+ld]
                              + Wv[ld*3+1]*Pv[(lr+1)*64+ld]
                              + Wv[ld*3+0]*Pv[lr*64+ld];
            Vs[lr][ld] = vv;
        }
        __syncthreads();
#pragma unroll 4
        for (int s = 0; s < 32; s++) {
            float kd = Ks[s][d];
            ksum += kd;
#pragma unroll
            for (int j = 0; j < 16; j++)
                acc[j] += kd * Vs[s][e0 + 4 * j];
        }
        __syncthreads();
    }

    float* kvout = g_KVpart + (((size_t)split * NBH + bh) * HD + d) * HD;
#pragma unroll
    for (int j = 0; j < 16; j++) kvout[e0 + 4 * j] = acc[j];
    if (e0 == 0) g_Ksump[((size_t)split * NBH + bh) * HD + d] = ksum;
}

__global__ void kv_reduce_kernel()
{
    int i = blockIdx.x * blockDim.x + threadIdx.x;
    float s = 0.f;
#pragma unroll
    for (int p = 0; p < NSPLIT; p++) s += g_KVpart[(size_t)p * NBH * HD * HD + i];
    g_KV[i] = s;
    if (i < NBH * HD) {
        float s2 = 0.f;
#pragma unroll
        for (int p = 0; p < NSPLIT; p++) s2 += g_Ksump[p * NBH * HD + i];
        g_Ksum[i] = s2;
    }
}

// ============================================================
// V_new with inline conv+fmap; tf32-rounded output.
// ============================================================
__global__ __launch_bounds__(256)
void vnew_kernel(const float* __restrict__ pq, float* __restrict__ out,
                 const float* __restrict__ qcw, const float* __restrict__ qcb)
{
    const int bh = blockIdx.x;
    const int b = bh / HH, h = bh % HH;
    const int s0 = blockIdx.y * 32;

    __shared__ float KVs[64 * 64];
    __shared__ float Kss[64];
    __shared__ float Pq[34 * 64];
    __shared__ float Qs[32][64];
    __shared__ float Wq[192], Bq[64];

    const int t = threadIdx.x;
    if (t < 192) Wq[t] = qcw[t];
    if (t < 64)  Bq[t] = qcb[t];

    const float* kvsrc = g_KV + (size_t)bh * HD * HD;
#pragma unroll
    for (int r = 0; r < 16; r++) KVs[r * 256 + t] = kvsrc[r * 256 + t];
    if (t < 64) Kss[t] = g_Ksum[bh * HD + t] + EPS;

    const size_t base = (size_t)b * SS * DM + h * HD;
#pragma unroll
    for (int r = 0; r < 9; r++) {
        int li = r * 256 + t;
        if (li < 34 * 64) {
            int lr = li >> 6, ld = li & 63;
            int s = s0 - 2 + lr;
            Pq[li] = (s >= 0) ? pq[base + (size_t)s * DM + ld] : 0.f;
        }
    }
    __syncthreads();
#pragma unroll
    for (int r = 0; r < 8; r++) {
        int li = r * 256 + t;
        int lr = li >> 6, ld = li & 63;
        float q = Bq[ld] + Wq[ld*3+2]*Pq[(lr+2)*64+ld]
                         + Wq[ld*3+1]*Pq[(lr+1)*64+ld]
                         + Wq[ld*3+0]*Pq[lr*64+ld];
        Qs[lr][ld] = (q > 0.f) ? (q + 1.f) : expf(q);
    }
    __syncthreads();

    const int sl = t >> 3;
    const int e0 = (t & 7) * 8;

    float denom = 0.f;
#pragma unroll
    for (int dd = 0; dd < 64; dd++) denom += Qs[sl][dd] * Kss[dd];
    float zinv = 1.f / denom;

    float acc[8];
#pragma unroll
    for (int j = 0; j < 8; j++) acc[j] = 0.f;
#pragma unroll
    for (int dd = 0; dd < 64; dd++) {
        float qd = Qs[sl][dd];
#pragma unroll
        for (int j = 0; j < 8; j++) acc[j] += KVs[dd * 64 + e0 + j] * qd;
    }

    size_t ob = base + (size_t)(s0 + sl) * DM + e0;
#pragma unroll
    for (int j = 0; j < 8; j++) out[ob + j] = rtf(acc[j] * zinv);
}

// ============================================================
// Host: tensormap creation via driver entry point
// ============================================================
typedef CUresult (*EncodeTiledFn)(CUtensorMap*, CUtensorMapDataType, cuuint32_t, void*,
                                  const cuuint64_t*, const cuuint64_t*,
                                  const cuuint32_t*, const cuuint32_t*,
                                  CUtensorMapInterleave, CUtensorMapSwizzle,
                                  CUtensorMapL2promotion, CUtensorMapFloatOOBfill);

static bool make_map2d(EncodeTiledFn enc, CUtensorMap* m, const float* ptr,
                       uint64_t rows, uint32_t boxRows)
{
    cuuint64_t dims[2]    = {DM, rows};
    cuuint64_t strides[1] = {DM * sizeof(float)};
    cuuint32_t box[2]     = {BK, boxRows};
    cuuint32_t es[2]      = {1, 1};
    return enc(m, CU_TENSOR_MAP_DATA_TYPE_FLOAT32, 2, (void*)ptr,
               dims, strides, box, es,
               CU_TENSOR_MAP_INTERLEAVE_NONE, CU_TENSOR_MAP_SWIZZLE_128B,
               CU_TENSOR_MAP_L2_PROMOTION_L2_128B,
               CU_TENSOR_MAP_FLOAT_OOB_FILL_NONE) == CUDA_SUCCESS;
}

extern "C" void kernel_launch(void* const* d_in, const int* in_sizes, int n_in,
                              void* d_out, int out_size)
{
    const float* query = (const float*)d_in[0];
    const float* key   = (const float*)d_in[1];
    const float* value = (const float*)d_in[2];
    const float* q_w   = (const float*)d_in[3];
    const float* q_b   = (const float*)d_in[4];
    const float* k_w   = (const float*)d_in[5];
    const float* k_b   = (const float*)d_in[6];
    const float* v_w   = (const float*)d_in[7];
    const float* v_b   = (const float*)d_in[8];
    const float* o_w   = (const float*)d_in[9];
    const float* o_b   = (const float*)d_in[10];
    const float* qc_w  = (const float*)d_in[11];
    const float* qc_b  = (const float*)d_in[12];
    const float* kc_w  = (const float*)d_in[13];
    const float* kc_b  = (const float*)d_in[14];
    const float* vc_w  = (const float*)d_in[15];
    const float* vc_b  = (const float*)d_in[16];
    float* out = (float*)d_out;

    float *proj, *vnew, *rw;
    cudaGetSymbolAddress((void**)&proj, g_proj);
    cudaGetSymbolAddress((void**)&vnew, g_vnew);
    cudaGetSymbolAddress((void**)&rw,   g_rw);
    float* pq = proj;  float* pk = proj + (size_t)NEL;  float* pv = proj + 2 * (size_t)NEL;
    float* rqw = rw;                       float* rkw = rw + (size_t)DM * DM;
    float* rvw = rw + 2 * (size_t)DM * DM; float* row_ = rw + 3 * (size_t)DM * DM;

    cudaFuncSetAttribute(gemm_persist_kernel,
                         cudaFuncAttributeMaxDynamicSharedMemorySize, PSMEM);
    cudaFuncSetAttribute(gemm_tf32_kernel,
                         cudaFuncAttributeMaxDynamicSharedMemorySize, GEMM_SMEM);

    EncodeTiledFn enc = nullptr;
    {
        void* p = nullptr;
        cudaDriverEntryPointQueryResult qr;
        if (cudaGetDriverEntryPoint("cuTensorMapEncodeTiled", &p,
                                    cudaEnableDefault, &qr) == cudaSuccess && p)
            enc = (EncodeTiledFn)p;
    }

    CUtensorMap mAq{}, mAk{}, mAv{}, mAo{}, mWq{}, mWk{}, mWv{}, mWo{};
    bool use_tma = (enc != nullptr);
    if (use_tma) {
        use_tma = make_map2d(enc, &mAq, query, MTOT, TM)
               && make_map2d(enc, &mAk, key,   MTOT, TM)
               && make_map2d(enc, &mAv, value, MTOT, TM)
               && make_map2d(enc, &mAo, vnew,  MTOT, TM)
               && make_map2d(enc, &mWq, rqw,  DM, TN)
               && make_map2d(enc, &mWk, rkw,  DM, TN)
               && make_map2d(enc, &mWv, rvw,  DM, TN)
               && make_map2d(enc, &mWo, row_, DM, TN);
    }

    // launch 0: weight rounding
    round4_kernel<<<4 * (DM * DM / 4) / 256, 256>>>(
        (const float4*)q_w, (const float4*)k_w, (const float4*)v_w, (const float4*)o_w,
        (float4*)rw);

    // launches 1-4: dummies so ncu (-s 5 -c 1) profiles the first GEMM
    dummy_kernel<<<1, 32>>>(1);
    dummy_kernel<<<1, 32>>>(2);
    dummy_kernel<<<1, 32>>>(3);
    dummy_kernel<<<1, 32>>>(4);

    dim3 ggrid_tc(DM / TN, MTOT / TM);

#define LAUNCH_GEMM(MA, MW, Araw, Wr, Bias, Cout) do { \
        if (use_tma) \
            gemm_persist_kernel<<<GRID_P, 192, PSMEM>>>(MA, MW, Bias, Cout); \
        else \
            gemm_tf32_kernel<<<ggrid_tc, 128, GEMM_SMEM>>>(Araw, Wr, Bias, Cout); \
    } while (0)

    // launches 5-7: QKV projections
    LAUNCH_GEMM(mAq, mWq, query, rqw, q_b, pq);
    LAUNCH_GEMM(mAk, mWk, key,   rkw, k_b, pk);
    LAUNCH_GEMM(mAv, mWv, value, rvw, v_b, pv);

    // KV + Ksum (conv fused)
    kv_accum_kernel<<<dim3(NBH, NSPLIT), 256>>>(pk, pv, kc_w, kc_b, vc_w, vc_b);
    kv_reduce_kernel<<<(NBH * HD * HD) / 256, 256>>>();

    // V_new (conv_q fused)
    vnew_kernel<<<dim3(NBH, SS / 32), 256>>>(pq, vnew, qc_w, qc_b);

    // output projection
    LAUNCH_GEMM(mAo, mWo, vnew, row_, o_b, out);
#undef LAUNCH_GEMM
}